// round 1
// baseline (speedup 1.0000x reference)
#include <cuda_runtime.h>
#include <math.h>

#define S 2048
#define D 4096
#define H 32
#define HD 128
#define NEGV -1000000000.0f

// Scratch (static device globals -- no allocation allowed)
__device__ float g_q[S * D];
__device__ float g_k[S * D];
__device__ float g_v[S * D];
__device__ float g_ao[S * D];

// ---------------------------------------------------------------------------
// SGEMM: C[2048,4096] = A[2048,4096] @ B[4096,4096], all row-major fp32.
// 128x128 tile, BK=16, 256 threads, 8x8 per thread (split 4+4 for
// conflict-free LDS.128).
// ---------------------------------------------------------------------------
#define BM 128
#define BN 128
#define BK 16
#define AS_STRIDE 132

__global__ __launch_bounds__(256) void sgemm_kernel(
    const float* __restrict__ A, const float* __restrict__ B,
    float* __restrict__ C)
{
    __shared__ float As[BK * AS_STRIDE];
    __shared__ float Bs[BK * BN];

    const int tid = threadIdx.x;
    const int ty = tid >> 4;
    const int tx = tid & 15;
    const int bm = blockIdx.y * BM;
    const int bn = blockIdx.x * BN;

    float acc[8][8];
#pragma unroll
    for (int i = 0; i < 8; i++)
#pragma unroll
        for (int j = 0; j < 8; j++) acc[i][j] = 0.0f;

    for (int k0 = 0; k0 < D; k0 += BK) {
        // Load A tile (128 x 16) transposed into As[k][m]
#pragma unroll
        for (int l = 0; l < 2; l++) {
            int id = tid + l * 256;          // float4 id, 0..511
            int r  = id >> 2;                // 0..127
            int c4 = (id & 3) << 2;          // 0,4,8,12
            float4 v = *(const float4*)(A + (size_t)(bm + r) * D + k0 + c4);
            As[(c4 + 0) * AS_STRIDE + r] = v.x;
            As[(c4 + 1) * AS_STRIDE + r] = v.y;
            As[(c4 + 2) * AS_STRIDE + r] = v.z;
            As[(c4 + 3) * AS_STRIDE + r] = v.w;

            // Load B tile (16 x 128) natural layout
            int rb = id >> 5;                // 0..15
            int cb = (id & 31) << 2;         // 0..124
            *(float4*)(Bs + rb * BN + cb) =
                *(const float4*)(B + (size_t)(k0 + rb) * D + bn + cb);
        }
        __syncthreads();

#pragma unroll
        for (int kk = 0; kk < BK; kk++) {
            float a[8], b[8];
            *(float4*)(a)     = *(float4*)(As + kk * AS_STRIDE + ty * 4);
            *(float4*)(a + 4) = *(float4*)(As + kk * AS_STRIDE + 64 + ty * 4);
            *(float4*)(b)     = *(float4*)(Bs + kk * BN + tx * 4);
            *(float4*)(b + 4) = *(float4*)(Bs + kk * BN + 64 + tx * 4);
#pragma unroll
            for (int i = 0; i < 8; i++)
#pragma unroll
                for (int j = 0; j < 8; j++)
                    acc[i][j] = fmaf(a[i], b[j], acc[i][j]);
        }
        __syncthreads();
    }

#pragma unroll
    for (int i = 0; i < 8; i++) {
        int r = bm + ((i < 4) ? (ty * 4 + i) : (64 + ty * 4 + i - 4));
        float4 r0 = make_float4(acc[i][0], acc[i][1], acc[i][2], acc[i][3]);
        float4 r1 = make_float4(acc[i][4], acc[i][5], acc[i][6], acc[i][7]);
        *(float4*)(C + (size_t)r * D + bn + tx * 4)      = r0;
        *(float4*)(C + (size_t)r * D + bn + 64 + tx * 4) = r1;
    }
}

// ---------------------------------------------------------------------------
// RoPE over full D: pair (i, i+2048) per thread, in-place.
// ---------------------------------------------------------------------------
__global__ __launch_bounds__(256) void rope_kernel(
    float* __restrict__ x, const float* __restrict__ cosp,
    const float* __restrict__ sinp)
{
    int idx = blockIdx.x * blockDim.x + threadIdx.x;   // 0 .. S*2048-1
    int s = idx >> 11;
    int i = idx & 2047;
    size_t base = (size_t)s * D;
    float lo = x[base + i];
    float hi = x[base + i + 2048];
    float c1 = cosp[base + i];
    float s1 = sinp[base + i];
    float c2 = cosp[base + i + 2048];
    float s2 = sinp[base + i + 2048];
    x[base + i]        = lo * c1 - hi * s1;
    x[base + i + 2048] = hi * c2 + lo * s2;
}

// ---------------------------------------------------------------------------
// Flash-style attention, fp32. One CTA = 64 q-rows x 1 head.
// Mask is ANTI-causal: k <= q gets NEG. Chunks entirely masked contribute
// exactly 0 and are skipped, except for the last q-block (row S-1 is fully
// masked -> softmax over raw scores, needs all chunks).
// ---------------------------------------------------------------------------
#define PSTR 68

__global__ __launch_bounds__(256) void attn_kernel(
    const float* __restrict__ Q, const float* __restrict__ K,
    const float* __restrict__ V, const float* __restrict__ amask,
    float* __restrict__ O)
{
    extern __shared__ float sm[];
    float* Qs  = sm;                 // [128][64]  d-major
    float* KV  = sm + 128 * 64;      // Ks [128][64] OR Vs [64][128]
    float* Pst = sm + 2 * 128 * 64;  // [64 key][PSTR] (row-minor)

    const int tid = threadIdx.x;
    const int ty = tid >> 4;
    const int tx = tid & 15;
    const int qb = blockIdx.x * 64;
    const int h0 = blockIdx.y * HD;

    // Load Q block (64 x 128) transposed to Qs[d][m]
#pragma unroll
    for (int l = 0; l < 8; l++) {
        int id = tid + l * 256;      // float4 id, 0..2047
        int n  = id >> 5;            // 0..63
        int d4 = (id & 31) << 2;     // 0..124
        float4 v = *(const float4*)(Q + (size_t)(qb + n) * D + h0 + d4);
        Qs[(d4 + 0) * 64 + n] = v.x;
        Qs[(d4 + 1) * 64 + n] = v.y;
        Qs[(d4 + 2) * 64 + n] = v.z;
        Qs[(d4 + 3) * 64 + n] = v.w;
    }

    float o[4][8];
    float m[4], lsum[4];
#pragma unroll
    for (int i = 0; i < 4; i++) {
        m[i] = -INFINITY;
        lsum[i] = 0.0f;
#pragma unroll
        for (int j = 0; j < 8; j++) o[i][j] = 0.0f;
    }

    const int kc0 = (qb == S - 64) ? 0 : qb;

    for (int kc = kc0; kc < S; kc += 64) {
        __syncthreads();   // prev PV reads of KV done; Qs visible on 1st iter

        // Load K chunk transposed: KV[d][n]
#pragma unroll
        for (int l = 0; l < 8; l++) {
            int id = tid + l * 256;
            int n  = id >> 5;
            int d4 = (id & 31) << 2;
            float4 v = *(const float4*)(K + (size_t)(kc + n) * D + h0 + d4);
            KV[(d4 + 0) * 64 + n] = v.x;
            KV[(d4 + 1) * 64 + n] = v.y;
            KV[(d4 + 2) * 64 + n] = v.z;
            KV[(d4 + 3) * 64 + n] = v.w;
        }
        __syncthreads();

        // S = Qb @ Kc^T  (4x4 per thread)
        float s[4][4];
#pragma unroll
        for (int i = 0; i < 4; i++)
#pragma unroll
            for (int j = 0; j < 4; j++) s[i][j] = 0.0f;

#pragma unroll 8
        for (int kk = 0; kk < 128; kk++) {
            float a[4], b[4];
            *(float4*)a = *(float4*)(Qs + kk * 64 + ty * 4);
            *(float4*)b = *(float4*)(KV + kk * 64 + tx * 4);
#pragma unroll
            for (int i = 0; i < 4; i++)
#pragma unroll
                for (int j = 0; j < 4; j++)
                    s[i][j] = fmaf(a[i], b[j], s[i][j]);
        }

        // scale + masks + online softmax update
#pragma unroll
        for (int i = 0; i < 4; i++) {
            int qr = qb + ty * 4 + i;
            float mx = -INFINITY;
#pragma unroll
            for (int j = 0; j < 4; j++) {
                int key = kc + tx * 4 + j;
                float v = s[i][j] * 0.015625f + amask[(size_t)qr * S + key];
                if (key <= qr) v += NEGV;
                s[i][j] = v;
                mx = fmaxf(mx, v);
            }
#pragma unroll
            for (int w = 1; w < 16; w <<= 1)
                mx = fmaxf(mx, __shfl_xor_sync(0xffffffffu, mx, w));
            float mn = fmaxf(m[i], mx);
            float corr = __expf(m[i] - mn);
            float ls = 0.0f;
#pragma unroll
            for (int j = 0; j < 4; j++) {
                float p = __expf(s[i][j] - mn);
                ls += p;
                Pst[(tx * 4 + j) * PSTR + ty * 4 + i] = p;
            }
#pragma unroll
            for (int w = 1; w < 16; w <<= 1)
                ls += __shfl_xor_sync(0xffffffffu, ls, w);
            lsum[i] = lsum[i] * corr + ls;
            m[i] = mn;
#pragma unroll
            for (int j = 0; j < 8; j++) o[i][j] *= corr;
        }
        __syncthreads();  // Pst visible to all; all Ks reads finished

        // Load V chunk natural layout: KV[n][d] (overwrites Ks)
#pragma unroll
        for (int l = 0; l < 8; l++) {
            int id = tid + l * 256;
            int n  = id >> 5;
            int d4 = (id & 31) << 2;
            *(float4*)(KV + n * 128 + d4) =
                *(const float4*)(V + (size_t)(kc + n) * D + h0 + d4);
        }
        __syncthreads();

        // O += P @ Vc  (4x8 per thread)
#pragma unroll 8
        for (int kk = 0; kk < 64; kk++) {
            float p[4], vv[8];
            *(float4*)p        = *(float4*)(Pst + kk * PSTR + ty * 4);
            *(float4*)(vv)     = *(float4*)(KV + kk * 128 + tx * 4);
            *(float4*)(vv + 4) = *(float4*)(KV + kk * 128 + 64 + tx * 4);
#pragma unroll
            for (int i = 0; i < 4; i++)
#pragma unroll
                for (int j = 0; j < 8; j++)
                    o[i][j] = fmaf(p[i], vv[j], o[i][j]);
        }
    }

    // epilogue: divide by l, write to (s, h*128+d) layout
#pragma unroll
    for (int i = 0; i < 4; i++) {
        float inv = 1.0f / lsum[i];
        float4 r0 = make_float4(o[i][0] * inv, o[i][1] * inv,
                                o[i][2] * inv, o[i][3] * inv);
        float4 r1 = make_float4(o[i][4] * inv, o[i][5] * inv,
                                o[i][6] * inv, o[i][7] * inv);
        size_t base = (size_t)(qb + ty * 4 + i) * D + h0;
        *(float4*)(O + base + tx * 4)      = r0;
        *(float4*)(O + base + 64 + tx * 4) = r1;
    }
}

// ---------------------------------------------------------------------------
extern "C" void kernel_launch(void* const* d_in, const int* in_sizes, int n_in,
                              void* d_out, int out_size)
{
    const float* hidden = (const float*)d_in[0];
    const float* amask  = (const float*)d_in[1];
    const float* cosp   = (const float*)d_in[2];
    const float* sinp   = (const float*)d_in[3];
    const float* wq     = (const float*)d_in[4];
    const float* wk     = (const float*)d_in[5];
    const float* wv     = (const float*)d_in[6];
    const float* wo     = (const float*)d_in[7];
    float* out = (float*)d_out;

    float *q, *k, *v, *ao;
    cudaGetSymbolAddress((void**)&q,  g_q);
    cudaGetSymbolAddress((void**)&k,  g_k);
    cudaGetSymbolAddress((void**)&v,  g_v);
    cudaGetSymbolAddress((void**)&ao, g_ao);

    const int attn_smem = (128 * 64 + 128 * 64 + 64 * PSTR) * 4;  // 82944 B
    cudaFuncSetAttribute(attn_kernel,
                         cudaFuncAttributeMaxDynamicSharedMemorySize,
                         attn_smem);

    dim3 gemm_grid(D / BN, S / BM);   // (32, 16)
    sgemm_kernel<<<gemm_grid, 256>>>(hidden, wq, q);
    sgemm_kernel<<<gemm_grid, 256>>>(hidden, wk, k);
    sgemm_kernel<<<gemm_grid, 256>>>(hidden, wv, v);

    int nrope = S * (D / 2);
    rope_kernel<<<nrope / 256, 256>>>(q, cosp, sinp);
    rope_kernel<<<nrope / 256, 256>>>(k, cosp, sinp);

    attn_kernel<<<dim3(S / 64, H), 256, attn_smem>>>(q, k, v, amask, ao);

    sgemm_kernel<<<gemm_grid, 256>>>(ao, wo, out);
}

// round 3
// speedup vs baseline: 1.9061x; 1.9061x over previous
#include <cuda_runtime.h>
#include <math.h>
#include <cstdint>

#define S 2048
#define D 4096
#define H 32
#define HD 128
#define NEGV -1000000000.0f

// Scratch (static device globals -- no allocation allowed)
__device__ float g_q[S * D];
__device__ float g_k[S * D];
__device__ float g_v[S * D];
__device__ float g_ao[S * D];

// ---------------------------------------------------------------------------
// Helpers
// ---------------------------------------------------------------------------
__device__ __forceinline__ uint32_t smem_u32(const void* p) {
    return (uint32_t)__cvta_generic_to_shared(p);
}
__device__ __forceinline__ uint32_t cvt_tf32(float f) {
    uint32_t r;
    asm("cvt.rna.tf32.f32 %0, %1;" : "=r"(r) : "f"(f));
    return r;
}
#define CP_ASYNC16(dst_u32, src_ptr) \
    asm volatile("cp.async.cg.shared.global [%0], [%1], 16;" \
                 :: "r"(dst_u32), "l"(src_ptr))
#define CP_COMMIT() asm volatile("cp.async.commit_group;")
#define CP_WAIT(N)  asm volatile("cp.async.wait_group %0;" :: "n"(N))

// ---------------------------------------------------------------------------
// tf32 mma.sync GEMM: C[2048,4096] = A[2048,4096] @ B[4096,4096]
// A row-major [M][K], B row-major [K][N] (natural weight layout, no transpose)
// CTA tile 128x128, BK=32, 256 threads (8 warps, each 64x32),
// double-buffered smem via cp.async.
// ---------------------------------------------------------------------------
#define GBM 128
#define GBN 128
#define GBK 32
#define AKS 36            // A smem row stride (floats): bank = (4r+c)%32, clean
#define BNS 136           // B smem row stride (floats): bank = (8k+n)%32, clean
#define A_TILE (GBM * AKS)          // 4608 floats
#define B_TILE (GBK * BNS)          // 4352 floats
#define GEMM_SMEM ((2 * A_TILE + 2 * B_TILE) * 4)   // 71680 bytes

__global__ __launch_bounds__(256, 2) void mma_gemm_kernel(
    const float* __restrict__ A, const float* __restrict__ B,
    float* __restrict__ C)
{
    extern __shared__ float sm[];
    float* As[2] = { sm, sm + A_TILE };
    float* Bs[2] = { sm + 2 * A_TILE, sm + 2 * A_TILE + B_TILE };

    const int tid  = threadIdx.x;
    const int warp = tid >> 5;
    const int lane = tid & 31;
    const int lg   = lane >> 2;      // groupID (0..7)
    const int lt   = lane & 3;       // threadID-in-group (0..3)
    const int wm   = warp >> 2;      // 0..1  -> 64-row slab
    const int wn   = warp & 3;       // 0..3  -> 32-col slab
    const int bm   = blockIdx.y * GBM;
    const int bn   = blockIdx.x * GBN;

    float c[4][4][4];
#pragma unroll
    for (int mi = 0; mi < 4; mi++)
#pragma unroll
        for (int ni = 0; ni < 4; ni++)
#pragma unroll
            for (int r = 0; r < 4; r++) c[mi][ni][r] = 0.0f;

    // tile loaders (cp.async, 4 float4 each for A and B per thread)
    auto load_tile = [&](int kc, int buf) {
        const float* Ap = A + (size_t)bm * D + kc * GBK;
        uint32_t a_s = smem_u32(As[buf]);
#pragma unroll
        for (int i = 0; i < 4; i++) {
            int fid = tid + i * 256;            // 0..1023
            int r   = fid >> 3;                 // 0..127
            int c4  = (fid & 7) << 2;           // 0..28
            CP_ASYNC16(a_s + (uint32_t)(r * AKS + c4) * 4,
                       Ap + (size_t)r * D + c4);
        }
        const float* Bp = B + (size_t)(kc * GBK) * D + bn;
        uint32_t b_s = smem_u32(Bs[buf]);
#pragma unroll
        for (int i = 0; i < 4; i++) {
            int fid = tid + i * 256;
            int k   = fid >> 5;                 // 0..31
            int n4  = (fid & 31) << 2;          // 0..124
            CP_ASYNC16(b_s + (uint32_t)(k * BNS + n4) * 4,
                       Bp + (size_t)k * D + n4);
        }
    };

    const int nk = D / GBK;   // 128
    load_tile(0, 0);
    CP_COMMIT();

    for (int kc = 0; kc < nk; kc++) {
        const int buf = kc & 1;
        if (kc + 1 < nk) {
            load_tile(kc + 1, buf ^ 1);
            CP_COMMIT();
            CP_WAIT(1);
        } else {
            CP_WAIT(0);
        }
        __syncthreads();

        const float* Ab = As[buf];
        const float* Bb = Bs[buf];
#pragma unroll
        for (int ks = 0; ks < GBK / 8; ks++) {
            const int kk = ks * 8;
            uint32_t af[4][4];
#pragma unroll
            for (int mi = 0; mi < 4; mi++) {
                int r0 = wm * 64 + mi * 16 + lg;
                af[mi][0] = cvt_tf32(Ab[r0 * AKS + kk + lt]);
                af[mi][1] = cvt_tf32(Ab[(r0 + 8) * AKS + kk + lt]);
                af[mi][2] = cvt_tf32(Ab[r0 * AKS + kk + lt + 4]);
                af[mi][3] = cvt_tf32(Ab[(r0 + 8) * AKS + kk + lt + 4]);
            }
            uint32_t bf[4][2];
#pragma unroll
            for (int ni = 0; ni < 4; ni++) {
                int n0 = wn * 32 + ni * 8 + lg;
                bf[ni][0] = cvt_tf32(Bb[(kk + lt) * BNS + n0]);
                bf[ni][1] = cvt_tf32(Bb[(kk + lt + 4) * BNS + n0]);
            }
#pragma unroll
            for (int mi = 0; mi < 4; mi++)
#pragma unroll
                for (int ni = 0; ni < 4; ni++) {
                    asm volatile(
                        "mma.sync.aligned.m16n8k8.row.col.f32.tf32.tf32.f32 "
                        "{%0,%1,%2,%3}, {%4,%5,%6,%7}, {%8,%9}, {%0,%1,%2,%3};"
                        : "+f"(c[mi][ni][0]), "+f"(c[mi][ni][1]),
                          "+f"(c[mi][ni][2]), "+f"(c[mi][ni][3])
                        : "r"(af[mi][0]), "r"(af[mi][1]),
                          "r"(af[mi][2]), "r"(af[mi][3]),
                          "r"(bf[ni][0]), "r"(bf[ni][1]));
                }
        }
        __syncthreads();
    }

    // epilogue
#pragma unroll
    for (int mi = 0; mi < 4; mi++) {
        int r0 = bm + wm * 64 + mi * 16 + lg;
#pragma unroll
        for (int ni = 0; ni < 4; ni++) {
            int col = bn + wn * 32 + ni * 8 + lt * 2;
            *(float2*)(C + (size_t)r0 * D + col) =
                make_float2(c[mi][ni][0], c[mi][ni][1]);
            *(float2*)(C + (size_t)(r0 + 8) * D + col) =
                make_float2(c[mi][ni][2], c[mi][ni][3]);
        }
    }
}

// ---------------------------------------------------------------------------
// RoPE over full D: pair (i, i+2048) per thread, in-place.
// ---------------------------------------------------------------------------
__global__ __launch_bounds__(256) void rope_kernel(
    float* __restrict__ x, const float* __restrict__ cosp,
    const float* __restrict__ sinp)
{
    int idx = blockIdx.x * blockDim.x + threadIdx.x;
    int s = idx >> 11;
    int i = idx & 2047;
    size_t base = (size_t)s * D;
    float lo = x[base + i];
    float hi = x[base + i + 2048];
    float c1 = cosp[base + i];
    float s1 = sinp[base + i];
    float c2 = cosp[base + i + 2048];
    float s2 = sinp[base + i + 2048];
    x[base + i]        = lo * c1 - hi * s1;
    x[base + i + 2048] = hi * c2 + lo * s2;
}

// ---------------------------------------------------------------------------
// Flash-style attention, fp32 (unchanged, passing). One CTA = 64 q x 1 head.
// Anti-causal mask: k <= q gets NEG; fully-masked chunks skipped except for
// the last q-block (row S-1 fully masked -> needs all chunks).
// ---------------------------------------------------------------------------
#define PSTR 68

__global__ __launch_bounds__(256) void attn_kernel(
    const float* __restrict__ Q, const float* __restrict__ K,
    const float* __restrict__ V, const float* __restrict__ amask,
    float* __restrict__ O)
{
    extern __shared__ float sm[];
    float* Qs  = sm;
    float* KV  = sm + 128 * 64;
    float* Pst = sm + 2 * 128 * 64;

    const int tid = threadIdx.x;
    const int ty = tid >> 4;
    const int tx = tid & 15;
    const int qb = blockIdx.x * 64;
    const int h0 = blockIdx.y * HD;

#pragma unroll
    for (int l = 0; l < 8; l++) {
        int id = tid + l * 256;
        int n  = id >> 5;
        int d4 = (id & 31) << 2;
        float4 v = *(const float4*)(Q + (size_t)(qb + n) * D + h0 + d4);
        Qs[(d4 + 0) * 64 + n] = v.x;
        Qs[(d4 + 1) * 64 + n] = v.y;
        Qs[(d4 + 2) * 64 + n] = v.z;
        Qs[(d4 + 3) * 64 + n] = v.w;
    }

    float o[4][8];
    float m[4], lsum[4];
#pragma unroll
    for (int i = 0; i < 4; i++) {
        m[i] = -INFINITY;
        lsum[i] = 0.0f;
#pragma unroll
        for (int j = 0; j < 8; j++) o[i][j] = 0.0f;
    }

    const int kc0 = (qb == S - 64) ? 0 : qb;

    for (int kc = kc0; kc < S; kc += 64) {
        __syncthreads();
#pragma unroll
        for (int l = 0; l < 8; l++) {
            int id = tid + l * 256;
            int n  = id >> 5;
            int d4 = (id & 31) << 2;
            float4 v = *(const float4*)(K + (size_t)(kc + n) * D + h0 + d4);
            KV[(d4 + 0) * 64 + n] = v.x;
            KV[(d4 + 1) * 64 + n] = v.y;
            KV[(d4 + 2) * 64 + n] = v.z;
            KV[(d4 + 3) * 64 + n] = v.w;
        }
        __syncthreads();

        float s[4][4];
#pragma unroll
        for (int i = 0; i < 4; i++)
#pragma unroll
            for (int j = 0; j < 4; j++) s[i][j] = 0.0f;

#pragma unroll 8
        for (int kk = 0; kk < 128; kk++) {
            float a[4], b[4];
            *(float4*)a = *(float4*)(Qs + kk * 64 + ty * 4);
            *(float4*)b = *(float4*)(KV + kk * 64 + tx * 4);
#pragma unroll
            for (int i = 0; i < 4; i++)
#pragma unroll
                for (int j = 0; j < 4; j++)
                    s[i][j] = fmaf(a[i], b[j], s[i][j]);
        }

#pragma unroll
        for (int i = 0; i < 4; i++) {
            int qr = qb + ty * 4 + i;
            float mx = -INFINITY;
#pragma unroll
            for (int j = 0; j < 4; j++) {
                int key = kc + tx * 4 + j;
                float v = s[i][j] * 0.015625f + amask[(size_t)qr * S + key];
                if (key <= qr) v += NEGV;
                s[i][j] = v;
                mx = fmaxf(mx, v);
            }
#pragma unroll
            for (int w = 1; w < 16; w <<= 1)
                mx = fmaxf(mx, __shfl_xor_sync(0xffffffffu, mx, w));
            float mn = fmaxf(m[i], mx);
            float corr = __expf(m[i] - mn);
            float ls = 0.0f;
#pragma unroll
            for (int j = 0; j < 4; j++) {
                float p = __expf(s[i][j] - mn);
                ls += p;
                Pst[(tx * 4 + j) * PSTR + ty * 4 + i] = p;
            }
#pragma unroll
            for (int w = 1; w < 16; w <<= 1)
                ls += __shfl_xor_sync(0xffffffffu, ls, w);
            lsum[i] = lsum[i] * corr + ls;
            m[i] = mn;
#pragma unroll
            for (int j = 0; j < 8; j++) o[i][j] *= corr;
        }
        __syncthreads();

#pragma unroll
        for (int l = 0; l < 8; l++) {
            int id = tid + l * 256;
            int n  = id >> 5;
            int d4 = (id & 31) << 2;
            *(float4*)(KV + n * 128 + d4) =
                *(const float4*)(V + (size_t)(kc + n) * D + h0 + d4);
        }
        __syncthreads();

#pragma unroll 8
        for (int kk = 0; kk < 64; kk++) {
            float p[4], vv[8];
            *(float4*)p        = *(float4*)(Pst + kk * PSTR + ty * 4);
            *(float4*)(vv)     = *(float4*)(KV + kk * 128 + tx * 4);
            *(float4*)(vv + 4) = *(float4*)(KV + kk * 128 + 64 + tx * 4);
#pragma unroll
            for (int i = 0; i < 4; i++)
#pragma unroll
                for (int j = 0; j < 8; j++)
                    o[i][j] = fmaf(p[i], vv[j], o[i][j]);
        }
    }

#pragma unroll
    for (int i = 0; i < 4; i++) {
        float inv = 1.0f / lsum[i];
        float4 r0 = make_float4(o[i][0] * inv, o[i][1] * inv,
                                o[i][2] * inv, o[i][3] * inv);
        float4 r1 = make_float4(o[i][4] * inv, o[i][5] * inv,
                                o[i][6] * inv, o[i][7] * inv);
        size_t base = (size_t)(qb + ty * 4 + i) * D + h0;
        *(float4*)(O + base + tx * 4)      = r0;
        *(float4*)(O + base + 64 + tx * 4) = r1;
    }
}

// ---------------------------------------------------------------------------
extern "C" void kernel_launch(void* const* d_in, const int* in_sizes, int n_in,
                              void* d_out, int out_size)
{
    const float* hidden = (const float*)d_in[0];
    const float* amask  = (const float*)d_in[1];
    const float* cosp   = (const float*)d_in[2];
    const float* sinp   = (const float*)d_in[3];
    const float* wq     = (const float*)d_in[4];
    const float* wk     = (const float*)d_in[5];
    const float* wv     = (const float*)d_in[6];
    const float* wo     = (const float*)d_in[7];
    float* out = (float*)d_out;

    float *q, *k, *v, *ao;
    cudaGetSymbolAddress((void**)&q,  g_q);
    cudaGetSymbolAddress((void**)&k,  g_k);
    cudaGetSymbolAddress((void**)&v,  g_v);
    cudaGetSymbolAddress((void**)&ao, g_ao);

    const int attn_smem = (128 * 64 + 128 * 64 + 64 * PSTR) * 4;
    cudaFuncSetAttribute(attn_kernel,
                         cudaFuncAttributeMaxDynamicSharedMemorySize, attn_smem);
    cudaFuncSetAttribute(mma_gemm_kernel,
                         cudaFuncAttributeMaxDynamicSharedMemorySize, GEMM_SMEM);

    dim3 ggrid(D / GBN, S / GBM);   // (32, 16)
    mma_gemm_kernel<<<ggrid, 256, GEMM_SMEM>>>(hidden, wq, q);
    mma_gemm_kernel<<<ggrid, 256, GEMM_SMEM>>>(hidden, wk, k);
    mma_gemm_kernel<<<ggrid, 256, GEMM_SMEM>>>(hidden, wv, v);

    int nrope = S * (D / 2);
    rope_kernel<<<nrope / 256, 256>>>(q, cosp, sinp);
    rope_kernel<<<nrope / 256, 256>>>(k, cosp, sinp);

    attn_kernel<<<dim3(S / 64, H), 256, attn_smem>>>(q, k, v, amask, ao);

    mma_gemm_kernel<<<ggrid, 256, GEMM_SMEM>>>(ao, wo, out);
}

// round 4
// speedup vs baseline: 2.0871x; 1.0949x over previous
#include <cuda_runtime.h>
#include <math.h>
#include <cstdint>

#define S 2048
#define D 4096
#define H 32
#define HD 128
#define NEGV -1000000000.0f

// Scratch (static device globals -- no allocation allowed)
__device__ float g_q[S * D];
__device__ float g_k[S * D];
__device__ float g_v[S * D];
__device__ float g_ao[S * D];
__device__ float g_h[S * D];                 // tf32-rounded hidden
__device__ float g_wt[4][(size_t)D * D];     // tf32-rounded weights

// ---------------------------------------------------------------------------
// Helpers
// ---------------------------------------------------------------------------
__device__ __forceinline__ uint32_t smem_u32(const void* p) {
    return (uint32_t)__cvta_generic_to_shared(p);
}
__device__ __forceinline__ uint32_t cvt_tf32(float f) {
    uint32_t r;
    asm("cvt.rna.tf32.f32 %0, %1;" : "=r"(r) : "f"(f));
    return r;
}
#define CP_ASYNC16(dst_u32, src_ptr) \
    asm volatile("cp.async.cg.shared.global [%0], [%1], 16;" \
                 :: "r"(dst_u32), "l"(src_ptr))
#define CP_COMMIT() asm volatile("cp.async.commit_group;")
#define CP_WAIT(N)  asm volatile("cp.async.wait_group %0;" :: "n"(N))

// ---------------------------------------------------------------------------
// tf32 pre-round pass: out[i] = round_rna_tf32(in[i])  (vectorized float4)
// ---------------------------------------------------------------------------
__global__ __launch_bounds__(256) void round_tf32_kernel(
    const float* __restrict__ in, float* __restrict__ out)
{
    size_t i = ((size_t)blockIdx.x * 256 + threadIdx.x) * 4;
    float4 v = *(const float4*)(in + i);
    uint4 r;
    r.x = cvt_tf32(v.x); r.y = cvt_tf32(v.y);
    r.z = cvt_tf32(v.z); r.w = cvt_tf32(v.w);
    *(uint4*)(out + i) = r;
}

// ---------------------------------------------------------------------------
// tf32 mma.sync GEMM (inputs pre-rounded to tf32 bit patterns; fragments are
// loaded raw -- HW truncation is then exact).
// C[2048,4096] = A[2048,4096] @ B[4096,4096], A [M][K] rm, B [K][N] rm.
// CTA tile 128x128, BK=32, 256 threads (8 warps, 64x32 each),
// 3-stage cp.async pipeline. grid.z selects (B,C) pair for fused QKV.
// ---------------------------------------------------------------------------
#define GBM 128
#define GBN 128
#define GBK 32
#define AKS 36
#define BNS 136
#define A_TILE (GBM * AKS)          // 4608 floats
#define B_TILE (GBK * BNS)          // 4352 floats
#define NSTAGE 3
#define GEMM_SMEM (NSTAGE * (A_TILE + B_TILE) * 4)   // 107520 bytes

__global__ __launch_bounds__(256, 2) void mma_gemm_kernel(
    const float* __restrict__ A,
    const float* __restrict__ B0, const float* __restrict__ B1,
    const float* __restrict__ B2,
    float* __restrict__ C0, float* __restrict__ C1, float* __restrict__ C2)
{
    const float* B = (blockIdx.z == 0) ? B0 : (blockIdx.z == 1) ? B1 : B2;
    float*       C = (blockIdx.z == 0) ? C0 : (blockIdx.z == 1) ? C1 : C2;

    extern __shared__ float sm[];
    float* As[NSTAGE];
    float* Bs[NSTAGE];
#pragma unroll
    for (int s = 0; s < NSTAGE; s++) {
        As[s] = sm + s * A_TILE;
        Bs[s] = sm + NSTAGE * A_TILE + s * B_TILE;
    }

    const int tid  = threadIdx.x;
    const int warp = tid >> 5;
    const int lane = tid & 31;
    const int lg   = lane >> 2;
    const int lt   = lane & 3;
    const int wm   = warp >> 2;
    const int wn   = warp & 3;
    const int bm   = blockIdx.y * GBM;
    const int bn   = blockIdx.x * GBN;

    float c[4][4][4];
#pragma unroll
    for (int mi = 0; mi < 4; mi++)
#pragma unroll
        for (int ni = 0; ni < 4; ni++)
#pragma unroll
            for (int r = 0; r < 4; r++) c[mi][ni][r] = 0.0f;

    auto load_tile = [&](int kc, int buf) {
        const float* Ap = A + (size_t)bm * D + kc * GBK;
        uint32_t a_s = smem_u32(As[buf]);
#pragma unroll
        for (int i = 0; i < 4; i++) {
            int fid = tid + i * 256;
            int r   = fid >> 3;
            int c4  = (fid & 7) << 2;
            CP_ASYNC16(a_s + (uint32_t)(r * AKS + c4) * 4,
                       Ap + (size_t)r * D + c4);
        }
        const float* Bp = B + (size_t)(kc * GBK) * D + bn;
        uint32_t b_s = smem_u32(Bs[buf]);
#pragma unroll
        for (int i = 0; i < 4; i++) {
            int fid = tid + i * 256;
            int k   = fid >> 5;
            int n4  = (fid & 31) << 2;
            CP_ASYNC16(b_s + (uint32_t)(k * BNS + n4) * 4,
                       Bp + (size_t)k * D + n4);
        }
    };

    const int nk = D / GBK;   // 128
    load_tile(0, 0);
    CP_COMMIT();
    load_tile(1, 1);
    CP_COMMIT();

    for (int kc = 0; kc < nk; kc++) {
        const int buf = kc % NSTAGE;
        if (kc + 2 < nk) {
            load_tile(kc + 2, (kc + 2) % NSTAGE);
            CP_COMMIT();
            CP_WAIT(2);
        } else if (kc + 1 < nk) {
            CP_WAIT(1);
        } else {
            CP_WAIT(0);
        }
        __syncthreads();

        const uint32_t* Ab = (const uint32_t*)As[buf];
        const uint32_t* Bb = (const uint32_t*)Bs[buf];
#pragma unroll
        for (int ks = 0; ks < GBK / 8; ks++) {
            const int kk = ks * 8;
            uint32_t af[4][4];
#pragma unroll
            for (int mi = 0; mi < 4; mi++) {
                int r0 = wm * 64 + mi * 16 + lg;
                af[mi][0] = Ab[r0 * AKS + kk + lt];
                af[mi][1] = Ab[(r0 + 8) * AKS + kk + lt];
                af[mi][2] = Ab[r0 * AKS + kk + lt + 4];
                af[mi][3] = Ab[(r0 + 8) * AKS + kk + lt + 4];
            }
            uint32_t bf[4][2];
#pragma unroll
            for (int ni = 0; ni < 4; ni++) {
                int n0 = wn * 32 + ni * 8 + lg;
                bf[ni][0] = Bb[(kk + lt) * BNS + n0];
                bf[ni][1] = Bb[(kk + lt + 4) * BNS + n0];
            }
#pragma unroll
            for (int mi = 0; mi < 4; mi++)
#pragma unroll
                for (int ni = 0; ni < 4; ni++) {
                    asm volatile(
                        "mma.sync.aligned.m16n8k8.row.col.f32.tf32.tf32.f32 "
                        "{%0,%1,%2,%3}, {%4,%5,%6,%7}, {%8,%9}, {%0,%1,%2,%3};"
                        : "+f"(c[mi][ni][0]), "+f"(c[mi][ni][1]),
                          "+f"(c[mi][ni][2]), "+f"(c[mi][ni][3])
                        : "r"(af[mi][0]), "r"(af[mi][1]),
                          "r"(af[mi][2]), "r"(af[mi][3]),
                          "r"(bf[ni][0]), "r"(bf[ni][1]));
                }
        }
        __syncthreads();
    }

#pragma unroll
    for (int mi = 0; mi < 4; mi++) {
        int r0 = bm + wm * 64 + mi * 16 + lg;
#pragma unroll
        for (int ni = 0; ni < 4; ni++) {
            int col = bn + wn * 32 + ni * 8 + lt * 2;
            *(float2*)(C + (size_t)r0 * D + col) =
                make_float2(c[mi][ni][0], c[mi][ni][1]);
            *(float2*)(C + (size_t)(r0 + 8) * D + col) =
                make_float2(c[mi][ni][2], c[mi][ni][3]);
        }
    }
}

// ---------------------------------------------------------------------------
// RoPE over full D: pair (i, i+2048) per thread, in-place.
// ---------------------------------------------------------------------------
__global__ __launch_bounds__(256) void rope_kernel(
    float* __restrict__ x, const float* __restrict__ cosp,
    const float* __restrict__ sinp)
{
    int idx = blockIdx.x * blockDim.x + threadIdx.x;
    int s = idx >> 11;
    int i = idx & 2047;
    size_t base = (size_t)s * D;
    float lo = x[base + i];
    float hi = x[base + i + 2048];
    float c1 = cosp[base + i];
    float s1 = sinp[base + i];
    float c2 = cosp[base + i + 2048];
    float s2 = sinp[base + i + 2048];
    x[base + i]        = lo * c1 - hi * s1;
    x[base + i + 2048] = hi * c2 + lo * s2;
}

// ---------------------------------------------------------------------------
// Flash-style attention, fp32. One CTA = 64 q x 1 head.
// Anti-causal mask: k <= q gets NEG; fully-masked chunks skipped except for
// the last q-block. Epilogue writes ao PRE-ROUNDED to tf32 (feeds final GEMM).
// ---------------------------------------------------------------------------
#define PSTR 68

__global__ __launch_bounds__(256) void attn_kernel(
    const float* __restrict__ Q, const float* __restrict__ K,
    const float* __restrict__ V, const float* __restrict__ amask,
    float* __restrict__ O)
{
    extern __shared__ float sm[];
    float* Qs  = sm;
    float* KV  = sm + 128 * 64;
    float* Pst = sm + 2 * 128 * 64;

    const int tid = threadIdx.x;
    const int ty = tid >> 4;
    const int tx = tid & 15;
    const int qb = blockIdx.x * 64;
    const int h0 = blockIdx.y * HD;

#pragma unroll
    for (int l = 0; l < 8; l++) {
        int id = tid + l * 256;
        int n  = id >> 5;
        int d4 = (id & 31) << 2;
        float4 v = *(const float4*)(Q + (size_t)(qb + n) * D + h0 + d4);
        Qs[(d4 + 0) * 64 + n] = v.x;
        Qs[(d4 + 1) * 64 + n] = v.y;
        Qs[(d4 + 2) * 64 + n] = v.z;
        Qs[(d4 + 3) * 64 + n] = v.w;
    }

    float o[4][8];
    float m[4], lsum[4];
#pragma unroll
    for (int i = 0; i < 4; i++) {
        m[i] = -INFINITY;
        lsum[i] = 0.0f;
#pragma unroll
        for (int j = 0; j < 8; j++) o[i][j] = 0.0f;
    }

    const int kc0 = (qb == S - 64) ? 0 : qb;

    for (int kc = kc0; kc < S; kc += 64) {
        __syncthreads();
#pragma unroll
        for (int l = 0; l < 8; l++) {
            int id = tid + l * 256;
            int n  = id >> 5;
            int d4 = (id & 31) << 2;
            float4 v = *(const float4*)(K + (size_t)(kc + n) * D + h0 + d4);
            KV[(d4 + 0) * 64 + n] = v.x;
            KV[(d4 + 1) * 64 + n] = v.y;
            KV[(d4 + 2) * 64 + n] = v.z;
            KV[(d4 + 3) * 64 + n] = v.w;
        }
        __syncthreads();

        float s[4][4];
#pragma unroll
        for (int i = 0; i < 4; i++)
#pragma unroll
            for (int j = 0; j < 4; j++) s[i][j] = 0.0f;

#pragma unroll 8
        for (int kk = 0; kk < 128; kk++) {
            float a[4], b[4];
            *(float4*)a = *(float4*)(Qs + kk * 64 + ty * 4);
            *(float4*)b = *(float4*)(KV + kk * 64 + tx * 4);
#pragma unroll
            for (int i = 0; i < 4; i++)
#pragma unroll
                for (int j = 0; j < 4; j++)
                    s[i][j] = fmaf(a[i], b[j], s[i][j]);
        }

#pragma unroll
        for (int i = 0; i < 4; i++) {
            int qr = qb + ty * 4 + i;
            float mx = -INFINITY;
#pragma unroll
            for (int j = 0; j < 4; j++) {
                int key = kc + tx * 4 + j;
                float v = s[i][j] * 0.015625f + amask[(size_t)qr * S + key];
                if (key <= qr) v += NEGV;
                s[i][j] = v;
                mx = fmaxf(mx, v);
            }
#pragma unroll
            for (int w = 1; w < 16; w <<= 1)
                mx = fmaxf(mx, __shfl_xor_sync(0xffffffffu, mx, w));
            float mn = fmaxf(m[i], mx);
            float corr = __expf(m[i] - mn);
            float ls = 0.0f;
#pragma unroll
            for (int j = 0; j < 4; j++) {
                float p = __expf(s[i][j] - mn);
                ls += p;
                Pst[(tx * 4 + j) * PSTR + ty * 4 + i] = p;
            }
#pragma unroll
            for (int w = 1; w < 16; w <<= 1)
                ls += __shfl_xor_sync(0xffffffffu, ls, w);
            lsum[i] = lsum[i] * corr + ls;
            m[i] = mn;
#pragma unroll
            for (int j = 0; j < 8; j++) o[i][j] *= corr;
        }
        __syncthreads();

#pragma unroll
        for (int l = 0; l < 8; l++) {
            int id = tid + l * 256;
            int n  = id >> 5;
            int d4 = (id & 31) << 2;
            *(float4*)(KV + n * 128 + d4) =
                *(const float4*)(V + (size_t)(kc + n) * D + h0 + d4);
        }
        __syncthreads();

#pragma unroll 8
        for (int kk = 0; kk < 64; kk++) {
            float p[4], vv[8];
            *(float4*)p        = *(float4*)(Pst + kk * PSTR + ty * 4);
            *(float4*)(vv)     = *(float4*)(KV + kk * 128 + tx * 4);
            *(float4*)(vv + 4) = *(float4*)(KV + kk * 128 + 64 + tx * 4);
#pragma unroll
            for (int i = 0; i < 4; i++)
#pragma unroll
                for (int j = 0; j < 8; j++)
                    o[i][j] = fmaf(p[i], vv[j], o[i][j]);
        }
    }

    // epilogue: divide by l, round to tf32 (final GEMM consumes raw bits)
#pragma unroll
    for (int i = 0; i < 4; i++) {
        float inv = 1.0f / lsum[i];
        uint4 r0, r1;
        r0.x = cvt_tf32(o[i][0] * inv); r0.y = cvt_tf32(o[i][1] * inv);
        r0.z = cvt_tf32(o[i][2] * inv); r0.w = cvt_tf32(o[i][3] * inv);
        r1.x = cvt_tf32(o[i][4] * inv); r1.y = cvt_tf32(o[i][5] * inv);
        r1.z = cvt_tf32(o[i][6] * inv); r1.w = cvt_tf32(o[i][7] * inv);
        size_t base = (size_t)(qb + ty * 4 + i) * D + h0;
        *(uint4*)(O + base + tx * 4)      = r0;
        *(uint4*)(O + base + 64 + tx * 4) = r1;
    }
}

// ---------------------------------------------------------------------------
extern "C" void kernel_launch(void* const* d_in, const int* in_sizes, int n_in,
                              void* d_out, int out_size)
{
    const float* hidden = (const float*)d_in[0];
    const float* amask  = (const float*)d_in[1];
    const float* cosp   = (const float*)d_in[2];
    const float* sinp   = (const float*)d_in[3];
    const float* wq     = (const float*)d_in[4];
    const float* wk     = (const float*)d_in[5];
    const float* wv     = (const float*)d_in[6];
    const float* wo     = (const float*)d_in[7];
    float* out = (float*)d_out;

    float *q, *k, *v, *ao, *h, *wt;
    cudaGetSymbolAddress((void**)&q,  g_q);
    cudaGetSymbolAddress((void**)&k,  g_k);
    cudaGetSymbolAddress((void**)&v,  g_v);
    cudaGetSymbolAddress((void**)&ao, g_ao);
    cudaGetSymbolAddress((void**)&h,  g_h);
    cudaGetSymbolAddress((void**)&wt, g_wt);
    float* wtq = wt;
    float* wtk = wt + (size_t)D * D;
    float* wtv = wt + 2 * (size_t)D * D;
    float* wto = wt + 3 * (size_t)D * D;

    const int attn_smem = (128 * 64 + 128 * 64 + 64 * PSTR) * 4;
    cudaFuncSetAttribute(attn_kernel,
                         cudaFuncAttributeMaxDynamicSharedMemorySize, attn_smem);
    cudaFuncSetAttribute(mma_gemm_kernel,
                         cudaFuncAttributeMaxDynamicSharedMemorySize, GEMM_SMEM);

    // pre-round all GEMM operands to tf32 bit patterns
    const int rb_h = (S * D) / (256 * 4);       // 8192 blocks
    const int rb_w = (D * D) / (256 * 4);       // 16384 blocks
    round_tf32_kernel<<<rb_h, 256>>>(hidden, h);
    round_tf32_kernel<<<rb_w, 256>>>(wq, wtq);
    round_tf32_kernel<<<rb_w, 256>>>(wk, wtk);
    round_tf32_kernel<<<rb_w, 256>>>(wv, wtv);
    round_tf32_kernel<<<rb_w, 256>>>(wo, wto);

    // fused QKV projection (grid.z = 3)
    dim3 qkv_grid(D / GBN, S / GBM, 3);
    mma_gemm_kernel<<<qkv_grid, 256, GEMM_SMEM>>>(h, wtq, wtk, wtv, q, k, v);

    int nrope = S * (D / 2);
    rope_kernel<<<nrope / 256, 256>>>(q, cosp, sinp);
    rope_kernel<<<nrope / 256, 256>>>(k, cosp, sinp);

    attn_kernel<<<dim3(S / 64, H), 256, attn_smem>>>(q, k, v, amask, ao);

    dim3 o_grid(D / GBN, S / GBM, 1);
    mma_gemm_kernel<<<o_grid, 256, GEMM_SMEM>>>(ao, wto, wto, wto, out, out, out);
}

// round 5
// speedup vs baseline: 2.1690x; 1.0392x over previous
#include <cuda_runtime.h>
#include <math.h>
#include <cstdint>

#define S 2048
#define D 4096
#define H 32
#define HD 128
#define NEGV -1000000000.0f

// Scratch (static device globals -- no allocation allowed)
__device__ float g_q[S * D];
__device__ float g_k[S * D];
__device__ float g_v[S * D];
__device__ float g_ao[S * D];
__device__ float g_h[S * D];                 // tf32-rounded hidden
__device__ float g_wt[4][(size_t)D * D];     // tf32-rounded weights

// ---------------------------------------------------------------------------
// Helpers
// ---------------------------------------------------------------------------
__device__ __forceinline__ uint32_t smem_u32(const void* p) {
    return (uint32_t)__cvta_generic_to_shared(p);
}
__device__ __forceinline__ uint32_t cvt_tf32(float f) {
    uint32_t r;
    asm("cvt.rna.tf32.f32 %0, %1;" : "=r"(r) : "f"(f));
    return r;
}
#define MBAR_INIT(addr, cnt) \
    asm volatile("mbarrier.init.shared.b64 [%0], %1;" :: "r"(addr), "r"(cnt) : "memory")
#define MBAR_EXPECT_TX(addr, bytes) \
    asm volatile("mbarrier.arrive.expect_tx.shared.b64 _, [%0], %1;" \
                 :: "r"(addr), "r"(bytes) : "memory")
__device__ __forceinline__ void mbar_wait(uint32_t addr, uint32_t parity) {
    asm volatile(
        "{\n\t.reg .pred P;\n\t"
        "W%=:\n\t"
        "mbarrier.try_wait.parity.acquire.cta.shared::cta.b64 P, [%0], %1, 0x989680;\n\t"
        "@!P bra W%=;\n\t}"
        :: "r"(addr), "r"(parity) : "memory");
}
#define BULK_LD(dst, src, bytes, mbar) \
    asm volatile("cp.async.bulk.shared::cluster.global.mbarrier::complete_tx::bytes " \
                 "[%0], [%1], %2, [%3];" \
                 :: "r"(dst), "l"(src), "r"(bytes), "r"(mbar) : "memory")

// ---------------------------------------------------------------------------
// tf32 pre-round pass, all 5 tensors in one launch (y selects tensor).
// ---------------------------------------------------------------------------
__global__ __launch_bounds__(256) void round_tf32_kernel(
    const float* __restrict__ i0, const float* __restrict__ i1,
    const float* __restrict__ i2, const float* __restrict__ i3,
    const float* __restrict__ i4,
    float* __restrict__ o0, float* __restrict__ o1, float* __restrict__ o2,
    float* __restrict__ o3, float* __restrict__ o4)
{
    const int t = blockIdx.y;
    if (t == 0 && blockIdx.x >= 8192) return;   // hidden is 8M floats only
    const float* in  = (t == 0) ? i0 : (t == 1) ? i1 : (t == 2) ? i2
                                 : (t == 3) ? i3 : i4;
    float* out = (t == 0) ? o0 : (t == 1) ? o1 : (t == 2) ? o2
                           : (t == 3) ? o3 : o4;
    size_t i = ((size_t)blockIdx.x * 256 + threadIdx.x) * 4;
    float4 v = *(const float4*)(in + i);
    uint4 r;
    r.x = cvt_tf32(v.x); r.y = cvt_tf32(v.y);
    r.z = cvt_tf32(v.z); r.w = cvt_tf32(v.w);
    *(uint4*)(out + i) = r;
}

// ---------------------------------------------------------------------------
// tf32 mma.sync GEMM, tiles filled via cp.async.bulk (row-granular) + mbarrier.
// C[2048,4096] = A[2048,4096] @ B[4096,4096]; A [M][K] rm, B [K][N] rm.
// CTA 128x128, BK=32, 256 threads (8 warps, 64x32 each), 3-stage ring.
// Inputs pre-rounded to tf32 bit patterns -> numerics identical to R3/R4.
// ---------------------------------------------------------------------------
#define GBM 128
#define GBN 128
#define GBK 32
#define AKS 36                       // A smem row stride (floats) = 144 B
#define BNS 136                      // B smem row stride (floats) = 544 B
#define NSTAGE 3
#define A_STAGE_B (GBM * AKS * 4)    // 18432 B
#define B_STAGE_B (GBK * BNS * 4)    // 17408 B
#define SM_MB 0                      // 3 mbarriers (8 B each)
#define SM_A  128
#define SM_B  (SM_A + NSTAGE * A_STAGE_B)            // 55424
#define GEMM_SMEM (SM_B + NSTAGE * B_STAGE_B)        // 107648 B
#define TILE_TX (GBM * GBK * 4 + GBK * GBN * 4)      // 32768 B

__global__ __launch_bounds__(256, 2) void mma_gemm_kernel(
    const float* __restrict__ A,
    const float* __restrict__ B0, const float* __restrict__ B1,
    const float* __restrict__ B2,
    float* __restrict__ C0, float* __restrict__ C1, float* __restrict__ C2)
{
    const float* B = (blockIdx.z == 0) ? B0 : (blockIdx.z == 1) ? B1 : B2;
    float*       C = (blockIdx.z == 0) ? C0 : (blockIdx.z == 1) ? C1 : C2;

    extern __shared__ float sm[];
    const uint32_t smb = smem_u32(sm);

    const int tid  = threadIdx.x;
    const int warp = tid >> 5;
    const int lane = tid & 31;
    const int lg   = lane >> 2;
    const int lt   = lane & 3;
    const int wm   = warp >> 2;
    const int wn   = warp & 3;
    const int bm   = blockIdx.y * GBM;
    const int bn   = blockIdx.x * GBN;

    if (tid == 0) {
        MBAR_INIT(smb + SM_MB + 0,  1);
        MBAR_INIT(smb + SM_MB + 8,  1);
        MBAR_INIT(smb + SM_MB + 16, 1);
    }
    __syncthreads();

    // producer: warp-lane0s issue bulk row copies for tile kc into stage s
    auto issue = [&](int kc, int stg) {
        if (tid == 0)
            MBAR_EXPECT_TX(smb + SM_MB + stg * 8, (uint32_t)TILE_TX);
        if (lane == 0) {
            const uint32_t mb = smb + SM_MB + stg * 8;
            // A: 128 rows x 128 B; warp w handles rows 16w..16w+15
            const float* Ap = A + (size_t)bm * D + kc * GBK;
            uint32_t a_dst = smb + SM_A + stg * A_STAGE_B + (warp * 16) * (AKS * 4);
#pragma unroll
            for (int r = 0; r < 16; r++)
                BULK_LD(a_dst + r * (AKS * 4),
                        Ap + (size_t)(warp * 16 + r) * D, 128u, mb);
            // B: 32 rows x 512 B; warp w handles rows 4w..4w+3
            const float* Bp = B + (size_t)(kc * GBK) * D + bn;
            uint32_t b_dst = smb + SM_B + stg * B_STAGE_B + (warp * 4) * (BNS * 4);
#pragma unroll
            for (int r = 0; r < 4; r++)
                BULK_LD(b_dst + r * (BNS * 4),
                        Bp + (size_t)(warp * 4 + r) * D, 512u, mb);
        }
    };

    float c[4][4][4];
#pragma unroll
    for (int mi = 0; mi < 4; mi++)
#pragma unroll
        for (int ni = 0; ni < 4; ni++)
#pragma unroll
            for (int r = 0; r < 4; r++) c[mi][ni][r] = 0.0f;

    const int nk = D / GBK;   // 128
    issue(0, 0);
    issue(1, 1);
    issue(2, 2);

    for (int kc = 0; kc < nk; kc++) {
        const int stg = kc % NSTAGE;
        mbar_wait(smb + SM_MB + stg * 8, (uint32_t)((kc / NSTAGE) & 1));

        const uint32_t* Ab = (const uint32_t*)(sm + (SM_A + stg * A_STAGE_B) / 4);
        const uint32_t* Bb = (const uint32_t*)(sm + (SM_B + stg * B_STAGE_B) / 4);
#pragma unroll
        for (int ks = 0; ks < GBK / 8; ks++) {
            const int kk = ks * 8;
            uint32_t af[4][4];
#pragma unroll
            for (int mi = 0; mi < 4; mi++) {
                int r0 = wm * 64 + mi * 16 + lg;
                af[mi][0] = Ab[r0 * AKS + kk + lt];
                af[mi][1] = Ab[(r0 + 8) * AKS + kk + lt];
                af[mi][2] = Ab[r0 * AKS + kk + lt + 4];
                af[mi][3] = Ab[(r0 + 8) * AKS + kk + lt + 4];
            }
            uint32_t bf[4][2];
#pragma unroll
            for (int ni = 0; ni < 4; ni++) {
                int n0 = wn * 32 + ni * 8 + lg;
                bf[ni][0] = Bb[(kk + lt) * BNS + n0];
                bf[ni][1] = Bb[(kk + lt + 4) * BNS + n0];
            }
#pragma unroll
            for (int mi = 0; mi < 4; mi++)
#pragma unroll
                for (int ni = 0; ni < 4; ni++) {
                    asm volatile(
                        "mma.sync.aligned.m16n8k8.row.col.f32.tf32.tf32.f32 "
                        "{%0,%1,%2,%3}, {%4,%5,%6,%7}, {%8,%9}, {%0,%1,%2,%3};"
                        : "+f"(c[mi][ni][0]), "+f"(c[mi][ni][1]),
                          "+f"(c[mi][ni][2]), "+f"(c[mi][ni][3])
                        : "r"(af[mi][0]), "r"(af[mi][1]),
                          "r"(af[mi][2]), "r"(af[mi][3]),
                          "r"(bf[ni][0]), "r"(bf[ni][1]));
                }
        }
        __syncthreads();                  // all warps done reading stage stg
        if (kc + NSTAGE < nk)
            issue(kc + NSTAGE, stg);      // refill the freed stage
    }

#pragma unroll
    for (int mi = 0; mi < 4; mi++) {
        int r0 = bm + wm * 64 + mi * 16 + lg;
#pragma unroll
        for (int ni = 0; ni < 4; ni++) {
            int col = bn + wn * 32 + ni * 8 + lt * 2;
            *(float2*)(C + (size_t)r0 * D + col) =
                make_float2(c[mi][ni][0], c[mi][ni][1]);
            *(float2*)(C + (size_t)(r0 + 8) * D + col) =
                make_float2(c[mi][ni][2], c[mi][ni][3]);
        }
    }
}

// ---------------------------------------------------------------------------
// RoPE over full D: pair (i, i+2048) per thread, in-place.
// ---------------------------------------------------------------------------
__global__ __launch_bounds__(256) void rope_kernel(
    float* __restrict__ x, const float* __restrict__ cosp,
    const float* __restrict__ sinp)
{
    int idx = blockIdx.x * blockDim.x + threadIdx.x;
    int s = idx >> 11;
    int i = idx & 2047;
    size_t base = (size_t)s * D;
    float lo = x[base + i];
    float hi = x[base + i + 2048];
    float c1 = cosp[base + i];
    float s1 = sinp[base + i];
    float c2 = cosp[base + i + 2048];
    float s2 = sinp[base + i + 2048];
    x[base + i]        = lo * c1 - hi * s1;
    x[base + i + 2048] = hi * c2 + lo * s2;
}

// ---------------------------------------------------------------------------
// Flash-style attention, fp32. One CTA = 64 q x 1 head.
// Anti-causal mask: k <= q gets NEG; fully-masked chunks skipped except for
// the last q-block. Epilogue writes ao PRE-ROUNDED to tf32 (feeds final GEMM).
// ---------------------------------------------------------------------------
#define PSTR 68

__global__ __launch_bounds__(256) void attn_kernel(
    const float* __restrict__ Q, const float* __restrict__ K,
    const float* __restrict__ V, const float* __restrict__ amask,
    float* __restrict__ O)
{
    extern __shared__ float sm[];
    float* Qs  = sm;
    float* KV  = sm + 128 * 64;
    float* Pst = sm + 2 * 128 * 64;

    const int tid = threadIdx.x;
    const int ty = tid >> 4;
    const int tx = tid & 15;
    const int qb = blockIdx.x * 64;
    const int h0 = blockIdx.y * HD;

#pragma unroll
    for (int l = 0; l < 8; l++) {
        int id = tid + l * 256;
        int n  = id >> 5;
        int d4 = (id & 31) << 2;
        float4 v = *(const float4*)(Q + (size_t)(qb + n) * D + h0 + d4);
        Qs[(d4 + 0) * 64 + n] = v.x;
        Qs[(d4 + 1) * 64 + n] = v.y;
        Qs[(d4 + 2) * 64 + n] = v.z;
        Qs[(d4 + 3) * 64 + n] = v.w;
    }

    float o[4][8];
    float m[4], lsum[4];
#pragma unroll
    for (int i = 0; i < 4; i++) {
        m[i] = -INFINITY;
        lsum[i] = 0.0f;
#pragma unroll
        for (int j = 0; j < 8; j++) o[i][j] = 0.0f;
    }

    const int kc0 = (qb == S - 64) ? 0 : qb;

    for (int kc = kc0; kc < S; kc += 64) {
        __syncthreads();
#pragma unroll
        for (int l = 0; l < 8; l++) {
            int id = tid + l * 256;
            int n  = id >> 5;
            int d4 = (id & 31) << 2;
            float4 v = *(const float4*)(K + (size_t)(kc + n) * D + h0 + d4);
            KV[(d4 + 0) * 64 + n] = v.x;
            KV[(d4 + 1) * 64 + n] = v.y;
            KV[(d4 + 2) * 64 + n] = v.z;
            KV[(d4 + 3) * 64 + n] = v.w;
        }
        __syncthreads();

        float s[4][4];
#pragma unroll
        for (int i = 0; i < 4; i++)
#pragma unroll
            for (int j = 0; j < 4; j++) s[i][j] = 0.0f;

#pragma unroll 8
        for (int kk = 0; kk < 128; kk++) {
            float a[4], b[4];
            *(float4*)a = *(float4*)(Qs + kk * 64 + ty * 4);
            *(float4*)b = *(float4*)(KV + kk * 64 + tx * 4);
#pragma unroll
            for (int i = 0; i < 4; i++)
#pragma unroll
                for (int j = 0; j < 4; j++)
                    s[i][j] = fmaf(a[i], b[j], s[i][j]);
        }

#pragma unroll
        for (int i = 0; i < 4; i++) {
            int qr = qb + ty * 4 + i;
            float mx = -INFINITY;
#pragma unroll
            for (int j = 0; j < 4; j++) {
                int key = kc + tx * 4 + j;
                float v = s[i][j] * 0.015625f + amask[(size_t)qr * S + key];
                if (key <= qr) v += NEGV;
                s[i][j] = v;
                mx = fmaxf(mx, v);
            }
#pragma unroll
            for (int w = 1; w < 16; w <<= 1)
                mx = fmaxf(mx, __shfl_xor_sync(0xffffffffu, mx, w));
            float mn = fmaxf(m[i], mx);
            float corr = __expf(m[i] - mn);
            float ls = 0.0f;
#pragma unroll
            for (int j = 0; j < 4; j++) {
                float p = __expf(s[i][j] - mn);
                ls += p;
                Pst[(tx * 4 + j) * PSTR + ty * 4 + i] = p;
            }
#pragma unroll
            for (int w = 1; w < 16; w <<= 1)
                ls += __shfl_xor_sync(0xffffffffu, ls, w);
            lsum[i] = lsum[i] * corr + ls;
            m[i] = mn;
#pragma unroll
            for (int j = 0; j < 8; j++) o[i][j] *= corr;
        }
        __syncthreads();

#pragma unroll
        for (int l = 0; l < 8; l++) {
            int id = tid + l * 256;
            int n  = id >> 5;
            int d4 = (id & 31) << 2;
            *(float4*)(KV + n * 128 + d4) =
                *(const float4*)(V + (size_t)(kc + n) * D + h0 + d4);
        }
        __syncthreads();

#pragma unroll 8
        for (int kk = 0; kk < 64; kk++) {
            float p[4], vv[8];
            *(float4*)p        = *(float4*)(Pst + kk * PSTR + ty * 4);
            *(float4*)(vv)     = *(float4*)(KV + kk * 128 + tx * 4);
            *(float4*)(vv + 4) = *(float4*)(KV + kk * 128 + 64 + tx * 4);
#pragma unroll
            for (int i = 0; i < 4; i++)
#pragma unroll
                for (int j = 0; j < 8; j++)
                    o[i][j] = fmaf(p[i], vv[j], o[i][j]);
        }
    }

    // epilogue: divide by l, round to tf32 (final GEMM consumes raw bits)
#pragma unroll
    for (int i = 0; i < 4; i++) {
        float inv = 1.0f / lsum[i];
        uint4 r0, r1;
        r0.x = cvt_tf32(o[i][0] * inv); r0.y = cvt_tf32(o[i][1] * inv);
        r0.z = cvt_tf32(o[i][2] * inv); r0.w = cvt_tf32(o[i][3] * inv);
        r1.x = cvt_tf32(o[i][4] * inv); r1.y = cvt_tf32(o[i][5] * inv);
        r1.z = cvt_tf32(o[i][6] * inv); r1.w = cvt_tf32(o[i][7] * inv);
        size_t base = (size_t)(qb + ty * 4 + i) * D + h0;
        *(uint4*)(O + base + tx * 4)      = r0;
        *(uint4*)(O + base + 64 + tx * 4) = r1;
    }
}

// ---------------------------------------------------------------------------
extern "C" void kernel_launch(void* const* d_in, const int* in_sizes, int n_in,
                              void* d_out, int out_size)
{
    const float* hidden = (const float*)d_in[0];
    const float* amask  = (const float*)d_in[1];
    const float* cosp   = (const float*)d_in[2];
    const float* sinp   = (const float*)d_in[3];
    const float* wq     = (const float*)d_in[4];
    const float* wk     = (const float*)d_in[5];
    const float* wv     = (const float*)d_in[6];
    const float* wo     = (const float*)d_in[7];
    float* out = (float*)d_out;

    float *q, *k, *v, *ao, *h, *wt;
    cudaGetSymbolAddress((void**)&q,  g_q);
    cudaGetSymbolAddress((void**)&k,  g_k);
    cudaGetSymbolAddress((void**)&v,  g_v);
    cudaGetSymbolAddress((void**)&ao, g_ao);
    cudaGetSymbolAddress((void**)&h,  g_h);
    cudaGetSymbolAddress((void**)&wt, g_wt);
    float* wtq = wt;
    float* wtk = wt + (size_t)D * D;
    float* wtv = wt + 2 * (size_t)D * D;
    float* wto = wt + 3 * (size_t)D * D;

    const int attn_smem = (128 * 64 + 128 * 64 + 64 * PSTR) * 4;
    cudaFuncSetAttribute(attn_kernel,
                         cudaFuncAttributeMaxDynamicSharedMemorySize, attn_smem);
    cudaFuncSetAttribute(mma_gemm_kernel,
                         cudaFuncAttributeMaxDynamicSharedMemorySize, GEMM_SMEM);

    // pre-round all GEMM operands to tf32 bit patterns (one fused launch)
    round_tf32_kernel<<<dim3(16384, 5), 256>>>(
        hidden, wq, wk, wv, wo, h, wtq, wtk, wtv, wto);

    // fused QKV projection (grid.z = 3)
    dim3 qkv_grid(D / GBN, S / GBM, 3);
    mma_gemm_kernel<<<qkv_grid, 256, GEMM_SMEM>>>(h, wtq, wtk, wtv, q, k, v);

    int nrope = S * (D / 2);
    rope_kernel<<<nrope / 256, 256>>>(q, cosp, sinp);
    rope_kernel<<<nrope / 256, 256>>>(k, cosp, sinp);

    attn_kernel<<<dim3(S / 64, H), 256, attn_smem>>>(q, k, v, amask, ao);

    dim3 o_grid(D / GBN, S / GBM, 1);
    mma_gemm_kernel<<<o_grid, 256, GEMM_SMEM>>>(ao, wto, wto, wto, out, out, out);
}

// round 7
// speedup vs baseline: 3.3176x; 1.5296x over previous
#include <cuda_runtime.h>
#include <math.h>
#include <cstdint>

#define S 2048
#define D 4096
#define H 32
#define HD 128
#define NEGV -1000000000.0f

// Scratch (static device globals -- no allocation allowed)
__device__ float g_q[S * D];
__device__ float g_k[S * D];
__device__ float g_v[S * D];
__device__ float g_ao[S * D];
__device__ float g_h[S * D];                 // tf32-rounded hidden
__device__ float g_wt[4][(size_t)D * D];     // tf32-rounded weights

// ---------------------------------------------------------------------------
// Helpers
// ---------------------------------------------------------------------------
__device__ __forceinline__ uint32_t smem_u32(const void* p) {
    return (uint32_t)__cvta_generic_to_shared(p);
}
__device__ __forceinline__ uint32_t cvt_tf32(float f) {
    uint32_t r;
    asm("cvt.rna.tf32.f32 %0, %1;" : "=r"(r) : "f"(f));
    return r;
}
#define MBAR_INIT(addr, cnt) \
    asm volatile("mbarrier.init.shared.b64 [%0], %1;" :: "r"(addr), "r"(cnt) : "memory")
#define MBAR_EXPECT_TX(addr, bytes) \
    asm volatile("mbarrier.arrive.expect_tx.shared.b64 _, [%0], %1;" \
                 :: "r"(addr), "r"(bytes) : "memory")
__device__ __forceinline__ void mbar_wait(uint32_t addr, uint32_t parity) {
    asm volatile(
        "{\n\t.reg .pred P;\n\t"
        "W%=:\n\t"
        "mbarrier.try_wait.parity.acquire.cta.shared::cta.b64 P, [%0], %1, 0x989680;\n\t"
        "@!P bra W%=;\n\t}"
        :: "r"(addr), "r"(parity) : "memory");
}
#define BULK_LD(dst, src, bytes, mbar) \
    asm volatile("cp.async.bulk.shared::cluster.global.mbarrier::complete_tx::bytes " \
                 "[%0], [%1], %2, [%3];" \
                 :: "r"(dst), "l"(src), "r"(bytes), "r"(mbar) : "memory")

#define MMA_TF32(c0, c1, c2, c3, a0, a1, a2, a3, b0, b1) \
    asm volatile( \
        "mma.sync.aligned.m16n8k8.row.col.f32.tf32.tf32.f32 " \
        "{%0,%1,%2,%3}, {%4,%5,%6,%7}, {%8,%9}, {%0,%1,%2,%3};" \
        : "+f"(c0), "+f"(c1), "+f"(c2), "+f"(c3) \
        : "r"(a0), "r"(a1), "r"(a2), "r"(a3), "r"(b0), "r"(b1))

// ---------------------------------------------------------------------------
// tf32 pre-round pass, all 5 tensors in one launch (y selects tensor).
// ---------------------------------------------------------------------------
__global__ __launch_bounds__(256) void round_tf32_kernel(
    const float* __restrict__ i0, const float* __restrict__ i1,
    const float* __restrict__ i2, const float* __restrict__ i3,
    const float* __restrict__ i4,
    float* __restrict__ o0, float* __restrict__ o1, float* __restrict__ o2,
    float* __restrict__ o3, float* __restrict__ o4)
{
    const int t = blockIdx.y;
    if (t == 0 && blockIdx.x >= 8192) return;   // hidden is 8M floats only
    const float* in  = (t == 0) ? i0 : (t == 1) ? i1 : (t == 2) ? i2
                                 : (t == 3) ? i3 : i4;
    float* out = (t == 0) ? o0 : (t == 1) ? o1 : (t == 2) ? o2
                           : (t == 3) ? o3 : o4;
    size_t i = ((size_t)blockIdx.x * 256 + threadIdx.x) * 4;
    float4 v = *(const float4*)(in + i);
    uint4 r;
    r.x = cvt_tf32(v.x); r.y = cvt_tf32(v.y);
    r.z = cvt_tf32(v.z); r.w = cvt_tf32(v.w);
    *(uint4*)(out + i) = r;
}

// ---------------------------------------------------------------------------
// tf32 mma.sync GEMM (unchanged from R5): cp.async.bulk + mbarrier, 3 stages.
// ---------------------------------------------------------------------------
#define GBM 128
#define GBN 128
#define GBK 32
#define AKS 36
#define BNS 136
#define NSTAGE 3
#define A_STAGE_B (GBM * AKS * 4)
#define B_STAGE_B (GBK * BNS * 4)
#define SM_MB 0
#define SM_A  128
#define SM_B  (SM_A + NSTAGE * A_STAGE_B)
#define GEMM_SMEM (SM_B + NSTAGE * B_STAGE_B)
#define TILE_TX (GBM * GBK * 4 + GBK * GBN * 4)

__global__ __launch_bounds__(256, 2) void mma_gemm_kernel(
    const float* __restrict__ A,
    const float* __restrict__ B0, const float* __restrict__ B1,
    const float* __restrict__ B2,
    float* __restrict__ C0, float* __restrict__ C1, float* __restrict__ C2)
{
    const float* B = (blockIdx.z == 0) ? B0 : (blockIdx.z == 1) ? B1 : B2;
    float*       C = (blockIdx.z == 0) ? C0 : (blockIdx.z == 1) ? C1 : C2;

    extern __shared__ float sm[];
    const uint32_t smb = smem_u32(sm);

    const int tid  = threadIdx.x;
    const int warp = tid >> 5;
    const int lane = tid & 31;
    const int lg   = lane >> 2;
    const int lt   = lane & 3;
    const int wm   = warp >> 2;
    const int wn   = warp & 3;
    const int bm   = blockIdx.y * GBM;
    const int bn   = blockIdx.x * GBN;

    if (tid == 0) {
        MBAR_INIT(smb + SM_MB + 0,  1);
        MBAR_INIT(smb + SM_MB + 8,  1);
        MBAR_INIT(smb + SM_MB + 16, 1);
    }
    __syncthreads();

    auto issue = [&](int kc, int stg) {
        if (tid == 0)
            MBAR_EXPECT_TX(smb + SM_MB + stg * 8, (uint32_t)TILE_TX);
        if (lane == 0) {
            const uint32_t mb = smb + SM_MB + stg * 8;
            const float* Ap = A + (size_t)bm * D + kc * GBK;
            uint32_t a_dst = smb + SM_A + stg * A_STAGE_B + (warp * 16) * (AKS * 4);
#pragma unroll
            for (int r = 0; r < 16; r++)
                BULK_LD(a_dst + r * (AKS * 4),
                        Ap + (size_t)(warp * 16 + r) * D, 128u, mb);
            const float* Bp = B + (size_t)(kc * GBK) * D + bn;
            uint32_t b_dst = smb + SM_B + stg * B_STAGE_B + (warp * 4) * (BNS * 4);
#pragma unroll
            for (int r = 0; r < 4; r++)
                BULK_LD(b_dst + r * (BNS * 4),
                        Bp + (size_t)(warp * 4 + r) * D, 512u, mb);
        }
    };

    float c[4][4][4];
#pragma unroll
    for (int mi = 0; mi < 4; mi++)
#pragma unroll
        for (int ni = 0; ni < 4; ni++)
#pragma unroll
            for (int r = 0; r < 4; r++) c[mi][ni][r] = 0.0f;

    const int nk = D / GBK;
    issue(0, 0);
    issue(1, 1);
    issue(2, 2);

    for (int kc = 0; kc < nk; kc++) {
        const int stg = kc % NSTAGE;
        mbar_wait(smb + SM_MB + stg * 8, (uint32_t)((kc / NSTAGE) & 1));

        const uint32_t* Ab = (const uint32_t*)(sm + (SM_A + stg * A_STAGE_B) / 4);
        const uint32_t* Bb = (const uint32_t*)(sm + (SM_B + stg * B_STAGE_B) / 4);
#pragma unroll
        for (int ks = 0; ks < GBK / 8; ks++) {
            const int kk = ks * 8;
            uint32_t af[4][4];
#pragma unroll
            for (int mi = 0; mi < 4; mi++) {
                int r0 = wm * 64 + mi * 16 + lg;
                af[mi][0] = Ab[r0 * AKS + kk + lt];
                af[mi][1] = Ab[(r0 + 8) * AKS + kk + lt];
                af[mi][2] = Ab[r0 * AKS + kk + lt + 4];
                af[mi][3] = Ab[(r0 + 8) * AKS + kk + lt + 4];
            }
            uint32_t bf[4][2];
#pragma unroll
            for (int ni = 0; ni < 4; ni++) {
                int n0 = wn * 32 + ni * 8 + lg;
                bf[ni][0] = Bb[(kk + lt) * BNS + n0];
                bf[ni][1] = Bb[(kk + lt + 4) * BNS + n0];
            }
#pragma unroll
            for (int mi = 0; mi < 4; mi++)
#pragma unroll
                for (int ni = 0; ni < 4; ni++)
                    MMA_TF32(c[mi][ni][0], c[mi][ni][1], c[mi][ni][2], c[mi][ni][3],
                             af[mi][0], af[mi][1], af[mi][2], af[mi][3],
                             bf[ni][0], bf[ni][1]);
        }
        __syncthreads();
        if (kc + NSTAGE < nk)
            issue(kc + NSTAGE, stg);
    }

#pragma unroll
    for (int mi = 0; mi < 4; mi++) {
        int r0 = bm + wm * 64 + mi * 16 + lg;
#pragma unroll
        for (int ni = 0; ni < 4; ni++) {
            int col = bn + wn * 32 + ni * 8 + lt * 2;
            *(float2*)(C + (size_t)r0 * D + col) =
                make_float2(c[mi][ni][0], c[mi][ni][1]);
            *(float2*)(C + (size_t)(r0 + 8) * D + col) =
                make_float2(c[mi][ni][2], c[mi][ni][3]);
        }
    }
}

// ---------------------------------------------------------------------------
// RoPE over full D: pair (i, i+2048) per thread, in-place.
// ---------------------------------------------------------------------------
__global__ __launch_bounds__(256) void rope_kernel(
    float* __restrict__ x, const float* __restrict__ cosp,
    const float* __restrict__ sinp)
{
    int idx = blockIdx.x * blockDim.x + threadIdx.x;
    int s = idx >> 11;
    int i = idx & 2047;
    size_t base = (size_t)s * D;
    float lo = x[base + i];
    float hi = x[base + i + 2048];
    float c1 = cosp[base + i];
    float s1 = sinp[base + i];
    float c2 = cosp[base + i + 2048];
    float s2 = sinp[base + i + 2048];
    x[base + i]        = lo * c1 - hi * s1;
    x[base + i + 2048] = hi * c2 + lo * s2;
}

// ---------------------------------------------------------------------------
// Flash attention with mma.sync tf32.
// CTA = 128 q-rows x 1 head, 8 warps; warp w owns q-rows [16w, 16w+16).
// Chunk = 64 keys. Q fragments live in registers for the whole CTA.
// Pm smem stages the FULL 128x64 amask tile (8 x 256-thread float4 passes),
// then each element is overwritten by its owning thread with tf32 P.
// Anti-causal mask: key <= q gets NEG; fully-masked chunks skipped except
// for the last q-block (needs full scan). Output written tf32-rounded.
// ---------------------------------------------------------------------------
#define AQB 128
#define AKC 64
#define KVS 132                       // K/V smem row stride (floats)
#define PS  68                        // Pm row stride (floats)
#define ASM_K 0
#define ASM_V (AKC * KVS)
#define ASM_P (2 * AKC * KVS)
#define ATTN_SMEM ((2 * AKC * KVS + AQB * PS) * 4)   // 102400 B

__global__ __launch_bounds__(256, 1) void attn_kernel(
    const float* __restrict__ Q, const float* __restrict__ K,
    const float* __restrict__ V, const float* __restrict__ amask,
    float* __restrict__ O)
{
    extern __shared__ float sm[];
    float* Ks = sm + ASM_K;
    float* Vs = sm + ASM_V;
    float* Pm = sm + ASM_P;
    const uint32_t* Ksb = (const uint32_t*)Ks;
    const uint32_t* Vsb = (const uint32_t*)Vs;
    const uint32_t* Pmb = (const uint32_t*)Pm;

    const int tid  = threadIdx.x;
    const int w    = tid >> 5;
    const int lane = tid & 31;
    const int lg   = lane >> 2;
    const int lt   = lane & 3;
    const int qb   = blockIdx.x * AQB;
    const int h0   = blockIdx.y * HD;
    const int rl0  = w * 16 + lg;          // CTA-local q row (c0/c1)
    const int r0   = qb + rl0;             // global q row
    const int r1   = r0 + 8;

    // Q fragments in registers (16 k-steps x 4)
    uint32_t qf[16][4];
    {
        const float* Qp0 = Q + (size_t)r0 * D + h0;
        const float* Qp1 = Qp0 + 8 * (size_t)D;
#pragma unroll
        for (int ks = 0; ks < 16; ks++) {
            qf[ks][0] = cvt_tf32(Qp0[ks * 8 + lt]);
            qf[ks][1] = cvt_tf32(Qp1[ks * 8 + lt]);
            qf[ks][2] = cvt_tf32(Qp0[ks * 8 + lt + 4]);
            qf[ks][3] = cvt_tf32(Qp1[ks * 8 + lt + 4]);
        }
    }

    float o[16][4];
#pragma unroll
    for (int ni = 0; ni < 16; ni++)
#pragma unroll
        for (int r = 0; r < 4; r++) o[ni][r] = 0.0f;
    float m0 = -INFINITY, m1 = -INFINITY, l0 = 0.0f, l1 = 0.0f;

    const int kc0 = (qb == S - AQB) ? 0 : qb;

    for (int kc = kc0; kc < S; kc += AKC) {
        __syncthreads();
        // stage K, V (tf32-rounded)
#pragma unroll
        for (int l = 0; l < 8; l++) {
            int id = tid + l * 256;
            int r  = id >> 5;
            int c4 = (id & 31) << 2;
            float4 kv = *(const float4*)(K + (size_t)(kc + r) * D + h0 + c4);
            float4 vv = *(const float4*)(V + (size_t)(kc + r) * D + h0 + c4);
            uint4 kr, vr;
            kr.x = cvt_tf32(kv.x); kr.y = cvt_tf32(kv.y);
            kr.z = cvt_tf32(kv.z); kr.w = cvt_tf32(kv.w);
            vr.x = cvt_tf32(vv.x); vr.y = cvt_tf32(vv.y);
            vr.z = cvt_tf32(vv.z); vr.w = cvt_tf32(vv.w);
            *(uint4*)(Ks + r * KVS + c4) = kr;
            *(uint4*)(Vs + r * KVS + c4) = vr;
        }
        // stage amask tile: 128 rows x 64 cols = 2048 float4 -> 8 passes
#pragma unroll
        for (int l = 0; l < 8; l++) {
            int id = tid + l * 256;
            int r  = id >> 4;                 // 0..127
            int c4 = (id & 15) << 2;          // 0..60
            *(float4*)(Pm + r * PS + c4) =
                *(const float4*)(amask + (size_t)(qb + r) * S + kc + c4);
        }
        __syncthreads();

        // S = Q @ K^T  (8 n8-tiles over 64 keys)
        float s[8][4];
#pragma unroll
        for (int ni = 0; ni < 8; ni++)
#pragma unroll
            for (int r = 0; r < 4; r++) s[ni][r] = 0.0f;
#pragma unroll
        for (int ks = 0; ks < 16; ks++) {
            const int kk = ks * 8;
#pragma unroll
            for (int ni = 0; ni < 8; ni++) {
                uint32_t b0 = Ksb[(ni * 8 + lg) * KVS + kk + lt];
                uint32_t b1 = Ksb[(ni * 8 + lg) * KVS + kk + lt + 4];
                MMA_TF32(s[ni][0], s[ni][1], s[ni][2], s[ni][3],
                         qf[ks][0], qf[ks][1], qf[ks][2], qf[ks][3], b0, b1);
            }
        }

        // scale + amask + causal NEG, row max
        float mx0 = -INFINITY, mx1 = -INFINITY;
#pragma unroll
        for (int ni = 0; ni < 8; ni++) {
            int col = ni * 8 + lt * 2;
            int key = kc + col;
            float a00 = Pm[rl0 * PS + col], a01 = Pm[rl0 * PS + col + 1];
            float a10 = Pm[(rl0 + 8) * PS + col], a11 = Pm[(rl0 + 8) * PS + col + 1];
            float v0 = s[ni][0] * 0.015625f + a00;
            float v1 = s[ni][1] * 0.015625f + a01;
            float v2 = s[ni][2] * 0.015625f + a10;
            float v3 = s[ni][3] * 0.015625f + a11;
            if (key     <= r0) v0 += NEGV;
            if (key + 1 <= r0) v1 += NEGV;
            if (key     <= r1) v2 += NEGV;
            if (key + 1 <= r1) v3 += NEGV;
            s[ni][0] = v0; s[ni][1] = v1; s[ni][2] = v2; s[ni][3] = v3;
            mx0 = fmaxf(mx0, fmaxf(v0, v1));
            mx1 = fmaxf(mx1, fmaxf(v2, v3));
        }
        mx0 = fmaxf(mx0, __shfl_xor_sync(0xffffffffu, mx0, 1));
        mx0 = fmaxf(mx0, __shfl_xor_sync(0xffffffffu, mx0, 2));
        mx1 = fmaxf(mx1, __shfl_xor_sync(0xffffffffu, mx1, 1));
        mx1 = fmaxf(mx1, __shfl_xor_sync(0xffffffffu, mx1, 2));

        float nm0 = fmaxf(m0, mx0), nm1 = fmaxf(m1, mx1);
        float corr0 = __expf(m0 - nm0), corr1 = __expf(m1 - nm1);
        float ls0 = 0.0f, ls1 = 0.0f;
#pragma unroll
        for (int ni = 0; ni < 8; ni++) {
            int col = ni * 8 + lt * 2;
            float p0 = __expf(s[ni][0] - nm0);
            float p1 = __expf(s[ni][1] - nm0);
            float p2 = __expf(s[ni][2] - nm1);
            float p3 = __expf(s[ni][3] - nm1);
            ls0 += p0 + p1;
            ls1 += p2 + p3;
            Pm[rl0 * PS + col]           = __uint_as_float(cvt_tf32(p0));
            Pm[rl0 * PS + col + 1]       = __uint_as_float(cvt_tf32(p1));
            Pm[(rl0 + 8) * PS + col]     = __uint_as_float(cvt_tf32(p2));
            Pm[(rl0 + 8) * PS + col + 1] = __uint_as_float(cvt_tf32(p3));
        }
        ls0 += __shfl_xor_sync(0xffffffffu, ls0, 1);
        ls0 += __shfl_xor_sync(0xffffffffu, ls0, 2);
        ls1 += __shfl_xor_sync(0xffffffffu, ls1, 1);
        ls1 += __shfl_xor_sync(0xffffffffu, ls1, 2);
        l0 = l0 * corr0 + ls0;
        l1 = l1 * corr1 + ls1;
        m0 = nm0; m1 = nm1;
#pragma unroll
        for (int ni = 0; ni < 16; ni++) {
            o[ni][0] *= corr0; o[ni][1] *= corr0;
            o[ni][2] *= corr1; o[ni][3] *= corr1;
        }
        __syncwarp();

        // O += P @ V  (16 n8-tiles over 128 d)
#pragma unroll
        for (int ks = 0; ks < 8; ks++) {
            const int kk = ks * 8;
            uint32_t a0 = Pmb[rl0 * PS + kk + lt];
            uint32_t a1 = Pmb[(rl0 + 8) * PS + kk + lt];
            uint32_t a2 = Pmb[rl0 * PS + kk + lt + 4];
            uint32_t a3 = Pmb[(rl0 + 8) * PS + kk + lt + 4];
#pragma unroll
            for (int ni = 0; ni < 16; ni++) {
                uint32_t b0 = Vsb[(kk + lt) * KVS + ni * 8 + lg];
                uint32_t b1 = Vsb[(kk + lt + 4) * KVS + ni * 8 + lg];
                MMA_TF32(o[ni][0], o[ni][1], o[ni][2], o[ni][3],
                         a0, a1, a2, a3, b0, b1);
            }
        }
    }

    // epilogue: /l, tf32-round (feeds WO GEMM), write (s, h0+d)
    float inv0 = 1.0f / l0, inv1 = 1.0f / l1;
#pragma unroll
    for (int ni = 0; ni < 16; ni++) {
        int col = ni * 8 + lt * 2;
        uint2 w0, w1;
        w0.x = cvt_tf32(o[ni][0] * inv0); w0.y = cvt_tf32(o[ni][1] * inv0);
        w1.x = cvt_tf32(o[ni][2] * inv1); w1.y = cvt_tf32(o[ni][3] * inv1);
        *(uint2*)(O + (size_t)r0 * D + h0 + col) = w0;
        *(uint2*)(O + (size_t)r1 * D + h0 + col) = w1;
    }
}

// ---------------------------------------------------------------------------
extern "C" void kernel_launch(void* const* d_in, const int* in_sizes, int n_in,
                              void* d_out, int out_size)
{
    const float* hidden = (const float*)d_in[0];
    const float* amask  = (const float*)d_in[1];
    const float* cosp   = (const float*)d_in[2];
    const float* sinp   = (const float*)d_in[3];
    const float* wq     = (const float*)d_in[4];
    const float* wk     = (const float*)d_in[5];
    const float* wv     = (const float*)d_in[6];
    const float* wo     = (const float*)d_in[7];
    float* out = (float*)d_out;

    float *q, *k, *v, *ao, *h, *wt;
    cudaGetSymbolAddress((void**)&q,  g_q);
    cudaGetSymbolAddress((void**)&k,  g_k);
    cudaGetSymbolAddress((void**)&v,  g_v);
    cudaGetSymbolAddress((void**)&ao, g_ao);
    cudaGetSymbolAddress((void**)&h,  g_h);
    cudaGetSymbolAddress((void**)&wt, g_wt);
    float* wtq = wt;
    float* wtk = wt + (size_t)D * D;
    float* wtv = wt + 2 * (size_t)D * D;
    float* wto = wt + 3 * (size_t)D * D;

    cudaFuncSetAttribute(attn_kernel,
                         cudaFuncAttributeMaxDynamicSharedMemorySize, ATTN_SMEM);
    cudaFuncSetAttribute(mma_gemm_kernel,
                         cudaFuncAttributeMaxDynamicSharedMemorySize, GEMM_SMEM);

    // pre-round all GEMM operands to tf32 bit patterns (one fused launch)
    round_tf32_kernel<<<dim3(16384, 5), 256>>>(
        hidden, wq, wk, wv, wo, h, wtq, wtk, wtv, wto);

    // fused QKV projection (grid.z = 3)
    dim3 qkv_grid(D / GBN, S / GBM, 3);
    mma_gemm_kernel<<<qkv_grid, 256, GEMM_SMEM>>>(h, wtq, wtk, wtv, q, k, v);

    int nrope = S * (D / 2);
    rope_kernel<<<nrope / 256, 256>>>(q, cosp, sinp);
    rope_kernel<<<nrope / 256, 256>>>(k, cosp, sinp);

    attn_kernel<<<dim3(S / AQB, H), 256, ATTN_SMEM>>>(q, k, v, amask, ao);

    dim3 o_grid(D / GBN, S / GBM, 1);
    mma_gemm_kernel<<<o_grid, 256, GEMM_SMEM>>>(ao, wto, wto, wto, out, out, out);
}

// round 8
// speedup vs baseline: 4.1669x; 1.2560x over previous
#include <cuda_runtime.h>
#include <cuda_fp16.h>
#include <math.h>
#include <cstdint>

#define S 2048
#define D 4096
#define H 32
#define HD 128
#define NEGV -1000000000.0f

// Scratch (static device globals -- no allocation allowed)
__device__ float  g_q[S * D];
__device__ float  g_k[S * D];
__device__ float  g_v[S * D];
__device__ __half g_hh[S * D];                 // fp16 hidden [M][K]
__device__ __half g_wth[4][(size_t)D * D];     // fp16 transposed weights [N][K]
__device__ __half g_aoh[S * D];                // fp16 attention output

// ---------------------------------------------------------------------------
// Helpers
// ---------------------------------------------------------------------------
__device__ __forceinline__ uint32_t smem_u32(const void* p) {
    return (uint32_t)__cvta_generic_to_shared(p);
}
__device__ __forceinline__ uint32_t cvt_tf32(float f) {
    uint32_t r;
    asm("cvt.rna.tf32.f32 %0, %1;" : "=r"(r) : "f"(f));
    return r;
}
#define MBAR_INIT(addr, cnt) \
    asm volatile("mbarrier.init.shared.b64 [%0], %1;" :: "r"(addr), "r"(cnt) : "memory")
#define MBAR_EXPECT_TX(addr, bytes) \
    asm volatile("mbarrier.arrive.expect_tx.shared.b64 _, [%0], %1;" \
                 :: "r"(addr), "r"(bytes) : "memory")
__device__ __forceinline__ void mbar_wait(uint32_t addr, uint32_t parity) {
    asm volatile(
        "{\n\t.reg .pred P;\n\t"
        "W%=:\n\t"
        "mbarrier.try_wait.parity.acquire.cta.shared::cta.b64 P, [%0], %1, 0x989680;\n\t"
        "@!P bra W%=;\n\t}"
        :: "r"(addr), "r"(parity) : "memory");
}
#define BULK_LD(dst, src, bytes, mbar) \
    asm volatile("cp.async.bulk.shared::cluster.global.mbarrier::complete_tx::bytes " \
                 "[%0], [%1], %2, [%3];" \
                 :: "r"(dst), "l"(src), "r"(bytes), "r"(mbar) : "memory")

#define MMA_TF32(c0, c1, c2, c3, a0, a1, a2, a3, b0, b1) \
    asm volatile( \
        "mma.sync.aligned.m16n8k8.row.col.f32.tf32.tf32.f32 " \
        "{%0,%1,%2,%3}, {%4,%5,%6,%7}, {%8,%9}, {%0,%1,%2,%3};" \
        : "+f"(c0), "+f"(c1), "+f"(c2), "+f"(c3) \
        : "r"(a0), "r"(a1), "r"(a2), "r"(a3), "r"(b0), "r"(b1))

#define MMA_F16(c0, c1, c2, c3, a0, a1, a2, a3, b0, b1) \
    asm volatile( \
        "mma.sync.aligned.m16n8k16.row.col.f32.f16.f16.f32 " \
        "{%0,%1,%2,%3}, {%4,%5,%6,%7}, {%8,%9}, {%0,%1,%2,%3};" \
        : "+f"(c0), "+f"(c1), "+f"(c2), "+f"(c3) \
        : "r"(a0), "r"(a1), "r"(a2), "r"(a3), "r"(b0), "r"(b1))

// ---------------------------------------------------------------------------
// Pre-pass 1: hidden fp32 -> fp16 [M][K]
// ---------------------------------------------------------------------------
__global__ __launch_bounds__(256) void convert_h_kernel(
    const float* __restrict__ in, __half* __restrict__ out)
{
    size_t i = ((size_t)blockIdx.x * 256 + threadIdx.x) * 4;
    float4 v = *(const float4*)(in + i);
    __half2 h0 = __floats2half2_rn(v.x, v.y);
    __half2 h1 = __floats2half2_rn(v.z, v.w);
    uint2 pack;
    pack.x = *(uint32_t*)&h0;
    pack.y = *(uint32_t*)&h1;
    *(uint2*)(out + i) = pack;
}

// ---------------------------------------------------------------------------
// Pre-pass 2: weights fp32 [K][N] -> fp16 transposed [N][K]  (z selects W)
// ---------------------------------------------------------------------------
__global__ __launch_bounds__(256) void transpose_w_kernel(
    const float* __restrict__ w0, const float* __restrict__ w1,
    const float* __restrict__ w2, const float* __restrict__ w3,
    __half* __restrict__ outbase)
{
    const float* in = (blockIdx.z == 0) ? w0 : (blockIdx.z == 1) ? w1
                      : (blockIdx.z == 2) ? w2 : w3;
    __half* out = outbase + (size_t)blockIdx.z * D * D;
    __shared__ float t[32][33];
    const int tx = threadIdx.x, ty = threadIdx.y;
    const int bn = blockIdx.x * 32, bk = blockIdx.y * 32;
#pragma unroll
    for (int i = 0; i < 32; i += 8)
        t[ty + i][tx] = in[(size_t)(bk + ty + i) * D + bn + tx];
    __syncthreads();
#pragma unroll
    for (int i = 0; i < 32; i += 8)
        out[(size_t)(bn + ty + i) * D + bk + tx] = __float2half(t[tx][ty + i]);
}

// ---------------------------------------------------------------------------
// fp16 mma.sync GEMM: C[2048,4096] = A[2048,4096] @ W, with W given
// TRANSPOSED fp16 [N][K]. CTA 128x128, BK=64, 256 threads (8 warps, 64x32),
// 3-stage cp.async.bulk + mbarrier ring. C written fp32.
// ---------------------------------------------------------------------------
#define GBM 128
#define GBN 128
#define GBK 64
#define KS_H 72                       // smem row stride in halves (144 B)
#define NSTAGE 3
#define STAGE_B (128 * KS_H * 2)      // 18432 B (A and B tiles same shape)
#define SM_MB 0
#define SM_A  128
#define SM_B  (SM_A + NSTAGE * STAGE_B)
#define GEMM_SMEM (SM_B + NSTAGE * STAGE_B)          // 110720 B
#define TILE_TX (GBM * GBK * 2 + GBK * GBN * 2)      // 32768 B

__global__ __launch_bounds__(256, 2) void hgemm_kernel(
    const __half* __restrict__ A, const __half* __restrict__ Wt,
    size_t wstride,
    float* __restrict__ C0, float* __restrict__ C1, float* __restrict__ C2)
{
    const __half* B = Wt + (size_t)blockIdx.z * wstride;
    float* C = (blockIdx.z == 0) ? C0 : (blockIdx.z == 1) ? C1 : C2;

    extern __shared__ float sm[];
    const uint32_t smb = smem_u32(sm);

    const int tid  = threadIdx.x;
    const int warp = tid >> 5;
    const int lane = tid & 31;
    const int lg   = lane >> 2;
    const int lt   = lane & 3;
    const int wm   = warp >> 2;
    const int wn   = warp & 3;
    const int bm   = blockIdx.y * GBM;
    const int bn   = blockIdx.x * GBN;

    if (tid == 0) {
        MBAR_INIT(smb + SM_MB + 0,  1);
        MBAR_INIT(smb + SM_MB + 8,  1);
        MBAR_INIT(smb + SM_MB + 16, 1);
    }
    __syncthreads();

    // producer: warp-lane0s issue bulk row copies (A rows + transposed-B rows)
    auto issue = [&](int kc, int stg) {
        if (tid == 0)
            MBAR_EXPECT_TX(smb + SM_MB + stg * 8, (uint32_t)TILE_TX);
        if (lane == 0) {
            const uint32_t mb = smb + SM_MB + stg * 8;
            const __half* Ap = A + (size_t)bm * D + kc * GBK;
            uint32_t a_dst = smb + SM_A + stg * STAGE_B + (warp * 16) * (KS_H * 2);
#pragma unroll
            for (int r = 0; r < 16; r++)
                BULK_LD(a_dst + r * (KS_H * 2),
                        Ap + (size_t)(warp * 16 + r) * D, 128u, mb);
            const __half* Bp = B + (size_t)bn * D + kc * GBK;
            uint32_t b_dst = smb + SM_B + stg * STAGE_B + (warp * 16) * (KS_H * 2);
#pragma unroll
            for (int r = 0; r < 16; r++)
                BULK_LD(b_dst + r * (KS_H * 2),
                        Bp + (size_t)(warp * 16 + r) * D, 128u, mb);
        }
    };

    float c[4][4][4];
#pragma unroll
    for (int mi = 0; mi < 4; mi++)
#pragma unroll
        for (int ni = 0; ni < 4; ni++)
#pragma unroll
            for (int r = 0; r < 4; r++) c[mi][ni][r] = 0.0f;

    const int nk = D / GBK;   // 64
    issue(0, 0);
    issue(1, 1);
    issue(2, 2);

    for (int kc = 0; kc < nk; kc++) {
        const int stg = kc % NSTAGE;
        mbar_wait(smb + SM_MB + stg * 8, (uint32_t)((kc / NSTAGE) & 1));

        // uint32 views; row stride = KS_H/2 = 36 uint32s (conflict-free: 36*lg+lt)
        const uint32_t* Ab = (const uint32_t*)((const char*)sm + SM_A + stg * STAGE_B);
        const uint32_t* Bb = (const uint32_t*)((const char*)sm + SM_B + stg * STAGE_B);
#pragma unroll
        for (int ks = 0; ks < GBK / 16; ks++) {      // 4 K=16 steps
            const int k2 = ks * 8;                   // uint32 (half2) offset
            uint32_t af[4][4];
#pragma unroll
            for (int mi = 0; mi < 4; mi++) {
                int r0 = wm * 64 + mi * 16 + lg;
                af[mi][0] = Ab[r0 * 36 + k2 + lt];
                af[mi][1] = Ab[(r0 + 8) * 36 + k2 + lt];
                af[mi][2] = Ab[r0 * 36 + k2 + 4 + lt];
                af[mi][3] = Ab[(r0 + 8) * 36 + k2 + 4 + lt];
            }
            uint32_t bf[4][2];
#pragma unroll
            for (int ni = 0; ni < 4; ni++) {
                int n0 = wn * 32 + ni * 8 + lg;
                bf[ni][0] = Bb[n0 * 36 + k2 + lt];
                bf[ni][1] = Bb[n0 * 36 + k2 + 4 + lt];
            }
#pragma unroll
            for (int mi = 0; mi < 4; mi++)
#pragma unroll
                for (int ni = 0; ni < 4; ni++)
                    MMA_F16(c[mi][ni][0], c[mi][ni][1], c[mi][ni][2], c[mi][ni][3],
                            af[mi][0], af[mi][1], af[mi][2], af[mi][3],
                            bf[ni][0], bf[ni][1]);
        }
        __syncthreads();
        if (kc + NSTAGE < nk)
            issue(kc + NSTAGE, stg);
    }

#pragma unroll
    for (int mi = 0; mi < 4; mi++) {
        int r0 = bm + wm * 64 + mi * 16 + lg;
#pragma unroll
        for (int ni = 0; ni < 4; ni++) {
            int col = bn + wn * 32 + ni * 8 + lt * 2;
            *(float2*)(C + (size_t)r0 * D + col) =
                make_float2(c[mi][ni][0], c[mi][ni][1]);
            *(float2*)(C + (size_t)(r0 + 8) * D + col) =
                make_float2(c[mi][ni][2], c[mi][ni][3]);
        }
    }
}

// ---------------------------------------------------------------------------
// RoPE over full D: pair (i, i+2048) per thread, in-place (fp32 q/k).
// ---------------------------------------------------------------------------
__global__ __launch_bounds__(256) void rope_kernel(
    float* __restrict__ x, const float* __restrict__ cosp,
    const float* __restrict__ sinp)
{
    int idx = blockIdx.x * blockDim.x + threadIdx.x;
    int s = idx >> 11;
    int i = idx & 2047;
    size_t base = (size_t)s * D;
    float lo = x[base + i];
    float hi = x[base + i + 2048];
    float c1 = cosp[base + i];
    float s1 = sinp[base + i];
    float c2 = cosp[base + i + 2048];
    float s2 = sinp[base + i + 2048];
    x[base + i]        = lo * c1 - hi * s1;
    x[base + i + 2048] = hi * c2 + lo * s2;
}

// ---------------------------------------------------------------------------
// Flash attention with mma.sync tf32 (unchanged internals from R7 pass).
// Epilogue now writes fp16 (feeds fp16 WO GEMM).
// ---------------------------------------------------------------------------
#define AQB 128
#define AKC 64
#define KVS 132
#define PS  68
#define ASM_K 0
#define ASM_V (AKC * KVS)
#define ASM_P (2 * AKC * KVS)
#define ATTN_SMEM ((2 * AKC * KVS + AQB * PS) * 4)   // 102400 B

__global__ __launch_bounds__(256, 1) void attn_kernel(
    const float* __restrict__ Q, const float* __restrict__ K,
    const float* __restrict__ V, const float* __restrict__ amask,
    __half* __restrict__ O)
{
    extern __shared__ float sm[];
    float* Ks = sm + ASM_K;
    float* Vs = sm + ASM_V;
    float* Pm = sm + ASM_P;
    const uint32_t* Ksb = (const uint32_t*)Ks;
    const uint32_t* Vsb = (const uint32_t*)Vs;
    const uint32_t* Pmb = (const uint32_t*)Pm;

    const int tid  = threadIdx.x;
    const int w    = tid >> 5;
    const int lane = tid & 31;
    const int lg   = lane >> 2;
    const int lt   = lane & 3;
    const int qb   = blockIdx.x * AQB;
    const int h0   = blockIdx.y * HD;
    const int rl0  = w * 16 + lg;
    const int r0   = qb + rl0;
    const int r1   = r0 + 8;

    uint32_t qf[16][4];
    {
        const float* Qp0 = Q + (size_t)r0 * D + h0;
        const float* Qp1 = Qp0 + 8 * (size_t)D;
#pragma unroll
        for (int ks = 0; ks < 16; ks++) {
            qf[ks][0] = cvt_tf32(Qp0[ks * 8 + lt]);
            qf[ks][1] = cvt_tf32(Qp1[ks * 8 + lt]);
            qf[ks][2] = cvt_tf32(Qp0[ks * 8 + lt + 4]);
            qf[ks][3] = cvt_tf32(Qp1[ks * 8 + lt + 4]);
        }
    }

    float o[16][4];
#pragma unroll
    for (int ni = 0; ni < 16; ni++)
#pragma unroll
        for (int r = 0; r < 4; r++) o[ni][r] = 0.0f;
    float m0 = -INFINITY, m1 = -INFINITY, l0 = 0.0f, l1 = 0.0f;

    const int kc0 = (qb == S - AQB) ? 0 : qb;

    for (int kc = kc0; kc < S; kc += AKC) {
        __syncthreads();
#pragma unroll
        for (int l = 0; l < 8; l++) {
            int id = tid + l * 256;
            int r  = id >> 5;
            int c4 = (id & 31) << 2;
            float4 kv = *(const float4*)(K + (size_t)(kc + r) * D + h0 + c4);
            float4 vv = *(const float4*)(V + (size_t)(kc + r) * D + h0 + c4);
            uint4 kr, vr;
            kr.x = cvt_tf32(kv.x); kr.y = cvt_tf32(kv.y);
            kr.z = cvt_tf32(kv.z); kr.w = cvt_tf32(kv.w);
            vr.x = cvt_tf32(vv.x); vr.y = cvt_tf32(vv.y);
            vr.z = cvt_tf32(vv.z); vr.w = cvt_tf32(vv.w);
            *(uint4*)(Ks + r * KVS + c4) = kr;
            *(uint4*)(Vs + r * KVS + c4) = vr;
        }
#pragma unroll
        for (int l = 0; l < 8; l++) {
            int id = tid + l * 256;
            int r  = id >> 4;
            int c4 = (id & 15) << 2;
            *(float4*)(Pm + r * PS + c4) =
                *(const float4*)(amask + (size_t)(qb + r) * S + kc + c4);
        }
        __syncthreads();

        float s[8][4];
#pragma unroll
        for (int ni = 0; ni < 8; ni++)
#pragma unroll
            for (int r = 0; r < 4; r++) s[ni][r] = 0.0f;
#pragma unroll
        for (int ks = 0; ks < 16; ks++) {
            const int kk = ks * 8;
#pragma unroll
            for (int ni = 0; ni < 8; ni++) {
                uint32_t b0 = Ksb[(ni * 8 + lg) * KVS + kk + lt];
                uint32_t b1 = Ksb[(ni * 8 + lg) * KVS + kk + lt + 4];
                MMA_TF32(s[ni][0], s[ni][1], s[ni][2], s[ni][3],
                         qf[ks][0], qf[ks][1], qf[ks][2], qf[ks][3], b0, b1);
            }
        }

        float mx0 = -INFINITY, mx1 = -INFINITY;
#pragma unroll
        for (int ni = 0; ni < 8; ni++) {
            int col = ni * 8 + lt * 2;
            int key = kc + col;
            float a00 = Pm[rl0 * PS + col], a01 = Pm[rl0 * PS + col + 1];
            float a10 = Pm[(rl0 + 8) * PS + col], a11 = Pm[(rl0 + 8) * PS + col + 1];
            float v0 = s[ni][0] * 0.015625f + a00;
            float v1 = s[ni][1] * 0.015625f + a01;
            float v2 = s[ni][2] * 0.015625f + a10;
            float v3 = s[ni][3] * 0.015625f + a11;
            if (key     <= r0) v0 += NEGV;
            if (key + 1 <= r0) v1 += NEGV;
            if (key     <= r1) v2 += NEGV;
            if (key + 1 <= r1) v3 += NEGV;
            s[ni][0] = v0; s[ni][1] = v1; s[ni][2] = v2; s[ni][3] = v3;
            mx0 = fmaxf(mx0, fmaxf(v0, v1));
            mx1 = fmaxf(mx1, fmaxf(v2, v3));
        }
        mx0 = fmaxf(mx0, __shfl_xor_sync(0xffffffffu, mx0, 1));
        mx0 = fmaxf(mx0, __shfl_xor_sync(0xffffffffu, mx0, 2));
        mx1 = fmaxf(mx1, __shfl_xor_sync(0xffffffffu, mx1, 1));
        mx1 = fmaxf(mx1, __shfl_xor_sync(0xffffffffu, mx1, 2));

        float nm0 = fmaxf(m0, mx0), nm1 = fmaxf(m1, mx1);
        float corr0 = __expf(m0 - nm0), corr1 = __expf(m1 - nm1);
        float ls0 = 0.0f, ls1 = 0.0f;
#pragma unroll
        for (int ni = 0; ni < 8; ni++) {
            int col = ni * 8 + lt * 2;
            float p0 = __expf(s[ni][0] - nm0);
            float p1 = __expf(s[ni][1] - nm0);
            float p2 = __expf(s[ni][2] - nm1);
            float p3 = __expf(s[ni][3] - nm1);
            ls0 += p0 + p1;
            ls1 += p2 + p3;
            Pm[rl0 * PS + col]           = __uint_as_float(cvt_tf32(p0));
            Pm[rl0 * PS + col + 1]       = __uint_as_float(cvt_tf32(p1));
            Pm[(rl0 + 8) * PS + col]     = __uint_as_float(cvt_tf32(p2));
            Pm[(rl0 + 8) * PS + col + 1] = __uint_as_float(cvt_tf32(p3));
        }
        ls0 += __shfl_xor_sync(0xffffffffu, ls0, 1);
        ls0 += __shfl_xor_sync(0xffffffffu, ls0, 2);
        ls1 += __shfl_xor_sync(0xffffffffu, ls1, 1);
        ls1 += __shfl_xor_sync(0xffffffffu, ls1, 2);
        l0 = l0 * corr0 + ls0;
        l1 = l1 * corr1 + ls1;
        m0 = nm0; m1 = nm1;
#pragma unroll
        for (int ni = 0; ni < 16; ni++) {
            o[ni][0] *= corr0; o[ni][1] *= corr0;
            o[ni][2] *= corr1; o[ni][3] *= corr1;
        }
        __syncwarp();

#pragma unroll
        for (int ks = 0; ks < 8; ks++) {
            const int kk = ks * 8;
            uint32_t a0 = Pmb[rl0 * PS + kk + lt];
            uint32_t a1 = Pmb[(rl0 + 8) * PS + kk + lt];
            uint32_t a2 = Pmb[rl0 * PS + kk + lt + 4];
            uint32_t a3 = Pmb[(rl0 + 8) * PS + kk + lt + 4];
#pragma unroll
            for (int ni = 0; ni < 16; ni++) {
                uint32_t b0 = Vsb[(kk + lt) * KVS + ni * 8 + lg];
                uint32_t b1 = Vsb[(kk + lt + 4) * KVS + ni * 8 + lg];
                MMA_TF32(o[ni][0], o[ni][1], o[ni][2], o[ni][3],
                         a0, a1, a2, a3, b0, b1);
            }
        }
    }

    // epilogue: /l, convert to fp16 (feeds WO hgemm)
    float inv0 = 1.0f / l0, inv1 = 1.0f / l1;
#pragma unroll
    for (int ni = 0; ni < 16; ni++) {
        int col = ni * 8 + lt * 2;
        __half2 w0 = __floats2half2_rn(o[ni][0] * inv0, o[ni][1] * inv0);
        __half2 w1 = __floats2half2_rn(o[ni][2] * inv1, o[ni][3] * inv1);
        *(__half2*)(O + (size_t)r0 * D + h0 + col) = w0;
        *(__half2*)(O + (size_t)r1 * D + h0 + col) = w1;
    }
}

// ---------------------------------------------------------------------------
extern "C" void kernel_launch(void* const* d_in, const int* in_sizes, int n_in,
                              void* d_out, int out_size)
{
    const float* hidden = (const float*)d_in[0];
    const float* amask  = (const float*)d_in[1];
    const float* cosp   = (const float*)d_in[2];
    const float* sinp   = (const float*)d_in[3];
    const float* wq     = (const float*)d_in[4];
    const float* wk     = (const float*)d_in[5];
    const float* wv     = (const float*)d_in[6];
    const float* wo     = (const float*)d_in[7];
    float* out = (float*)d_out;

    float *q, *k, *v;
    __half *hh, *wth, *aoh;
    cudaGetSymbolAddress((void**)&q,   g_q);
    cudaGetSymbolAddress((void**)&k,   g_k);
    cudaGetSymbolAddress((void**)&v,   g_v);
    cudaGetSymbolAddress((void**)&hh,  g_hh);
    cudaGetSymbolAddress((void**)&wth, g_wth);
    cudaGetSymbolAddress((void**)&aoh, g_aoh);

    cudaFuncSetAttribute(attn_kernel,
                         cudaFuncAttributeMaxDynamicSharedMemorySize, ATTN_SMEM);
    cudaFuncSetAttribute(hgemm_kernel,
                         cudaFuncAttributeMaxDynamicSharedMemorySize, GEMM_SMEM);

    // pre-pass: fp16 conversions (hidden) + transposed fp16 weights
    convert_h_kernel<<<(S * D) / (256 * 4), 256>>>(hidden, hh);
    transpose_w_kernel<<<dim3(D / 32, D / 32, 4), dim3(32, 8)>>>(
        wq, wk, wv, wo, wth);

    // fused QKV projection (grid.z = 3 selects weight & output)
    dim3 qkv_grid(D / GBN, S / GBM, 3);
    hgemm_kernel<<<qkv_grid, 256, GEMM_SMEM>>>(
        hh, wth, (size_t)D * D, q, k, v);

    int nrope = S * (D / 2);
    rope_kernel<<<nrope / 256, 256>>>(q, cosp, sinp);
    rope_kernel<<<nrope / 256, 256>>>(k, cosp, sinp);

    attn_kernel<<<dim3(S / AQB, H), 256, ATTN_SMEM>>>(q, k, v, amask, aoh);

    // WO projection: A = fp16 attention output, W = wth[3]
    dim3 o_grid(D / GBN, S / GBM, 1);
    hgemm_kernel<<<o_grid, 256, GEMM_SMEM>>>(
        aoh, wth + 3 * (size_t)D * D, 0, out, out, out);
}

// round 9
// speedup vs baseline: 4.5580x; 1.0938x over previous
#include <cuda_runtime.h>
#include <cuda_fp16.h>
#include <math.h>
#include <cstdint>

#define S 2048
#define D 4096
#define H 32
#define HD 128
#define NEGV -1000000000.0f

// Scratch (static device globals -- no allocation allowed)
__device__ float  g_q[S * D];
__device__ float  g_k[S * D];
__device__ float  g_v[S * D];
__device__ __half g_hh[S * D];                 // fp16 hidden [M][K]
__device__ __half g_wth[4][(size_t)D * D];     // fp16 transposed weights [N][K]
__device__ __half g_aoh[S * D];                // fp16 attention output

// ---------------------------------------------------------------------------
// Helpers
// ---------------------------------------------------------------------------
__device__ __forceinline__ uint32_t smem_u32(const void* p) {
    return (uint32_t)__cvta_generic_to_shared(p);
}
__device__ __forceinline__ uint32_t cvt_tf32(float f) {
    uint32_t r;
    asm("cvt.rna.tf32.f32 %0, %1;" : "=r"(r) : "f"(f));
    return r;
}
#define MBAR_INIT(addr, cnt) \
    asm volatile("mbarrier.init.shared.b64 [%0], %1;" :: "r"(addr), "r"(cnt) : "memory")
#define MBAR_EXPECT_TX(addr, bytes) \
    asm volatile("mbarrier.arrive.expect_tx.shared.b64 _, [%0], %1;" \
                 :: "r"(addr), "r"(bytes) : "memory")
__device__ __forceinline__ void mbar_wait(uint32_t addr, uint32_t parity) {
    asm volatile(
        "{\n\t.reg .pred P;\n\t"
        "W%=:\n\t"
        "mbarrier.try_wait.parity.acquire.cta.shared::cta.b64 P, [%0], %1, 0x989680;\n\t"
        "@!P bra W%=;\n\t}"
        :: "r"(addr), "r"(parity) : "memory");
}
#define BULK_LD(dst, src, bytes, mbar) \
    asm volatile("cp.async.bulk.shared::cluster.global.mbarrier::complete_tx::bytes " \
                 "[%0], [%1], %2, [%3];" \
                 :: "r"(dst), "l"(src), "r"(bytes), "r"(mbar) : "memory")

#define MMA_TF32(c0, c1, c2, c3, a0, a1, a2, a3, b0, b1) \
    asm volatile( \
        "mma.sync.aligned.m16n8k8.row.col.f32.tf32.tf32.f32 " \
        "{%0,%1,%2,%3}, {%4,%5,%6,%7}, {%8,%9}, {%0,%1,%2,%3};" \
        : "+f"(c0), "+f"(c1), "+f"(c2), "+f"(c3) \
        : "r"(a0), "r"(a1), "r"(a2), "r"(a3), "r"(b0), "r"(b1))

#define MMA_F16(c0, c1, c2, c3, a0, a1, a2, a3, b0, b1) \
    asm volatile( \
        "mma.sync.aligned.m16n8k16.row.col.f32.f16.f16.f32 " \
        "{%0,%1,%2,%3}, {%4,%5,%6,%7}, {%8,%9}, {%0,%1,%2,%3};" \
        : "+f"(c0), "+f"(c1), "+f"(c2), "+f"(c3) \
        : "r"(a0), "r"(a1), "r"(a2), "r"(a3), "r"(b0), "r"(b1))

#define LDSM_X4(r0, r1, r2, r3, addr) \
    asm volatile("ldmatrix.sync.aligned.m8n8.x4.shared.b16 {%0,%1,%2,%3}, [%4];" \
                 : "=r"(r0), "=r"(r1), "=r"(r2), "=r"(r3) : "r"(addr))

// ---------------------------------------------------------------------------
// Pre-pass 1: hidden fp32 -> fp16 [M][K]
// ---------------------------------------------------------------------------
__global__ __launch_bounds__(256) void convert_h_kernel(
    const float* __restrict__ in, __half* __restrict__ out)
{
    size_t i = ((size_t)blockIdx.x * 256 + threadIdx.x) * 4;
    float4 v = *(const float4*)(in + i);
    __half2 h0 = __floats2half2_rn(v.x, v.y);
    __half2 h1 = __floats2half2_rn(v.z, v.w);
    uint2 pack;
    pack.x = *(uint32_t*)&h0;
    pack.y = *(uint32_t*)&h1;
    *(uint2*)(out + i) = pack;
}

// ---------------------------------------------------------------------------
// Pre-pass 2: weights fp32 [K][N] -> fp16 transposed [N][K]  (z selects W)
// ---------------------------------------------------------------------------
__global__ __launch_bounds__(256) void transpose_w_kernel(
    const float* __restrict__ w0, const float* __restrict__ w1,
    const float* __restrict__ w2, const float* __restrict__ w3,
    __half* __restrict__ outbase)
{
    const float* in = (blockIdx.z == 0) ? w0 : (blockIdx.z == 1) ? w1
                      : (blockIdx.z == 2) ? w2 : w3;
    __half* out = outbase + (size_t)blockIdx.z * D * D;
    __shared__ float t[32][33];
    const int tx = threadIdx.x, ty = threadIdx.y;
    const int bn = blockIdx.x * 32, bk = blockIdx.y * 32;
#pragma unroll
    for (int i = 0; i < 32; i += 8)
        t[ty + i][tx] = in[(size_t)(bk + ty + i) * D + bn + tx];
    __syncthreads();
#pragma unroll
    for (int i = 0; i < 32; i += 8)
        out[(size_t)(bn + ty + i) * D + bk + tx] = __float2half(t[tx][ty + i]);
}

// ---------------------------------------------------------------------------
// fp16 mma.sync GEMM with ldmatrix fragment loads.
// C[2048,4096] = A[2048,4096] @ W^T, W given TRANSPOSED fp16 [N][K].
// CTA 128x128, BK=64, 256 threads (8 warps, 64x32), 3-stage bulk ring.
// ---------------------------------------------------------------------------
#define GBM 128
#define GBN 128
#define GBK 64
#define KS_H 72                       // smem row stride in halves (144 B)
#define NSTAGE 3
#define STAGE_B (128 * KS_H * 2)      // 18432 B
#define SM_MB 0
#define SM_A  128
#define SM_B  (SM_A + NSTAGE * STAGE_B)
#define GEMM_SMEM (SM_B + NSTAGE * STAGE_B)          // 110720 B
#define TILE_TX (GBM * GBK * 2 + GBK * GBN * 2)      // 32768 B

__global__ __launch_bounds__(256, 2) void hgemm_kernel(
    const __half* __restrict__ A, const __half* __restrict__ Wt,
    size_t wstride,
    float* __restrict__ C0, float* __restrict__ C1, float* __restrict__ C2)
{
    const __half* B = Wt + (size_t)blockIdx.z * wstride;
    float* C = (blockIdx.z == 0) ? C0 : (blockIdx.z == 1) ? C1 : C2;

    extern __shared__ float sm[];
    const uint32_t smb = smem_u32(sm);

    const int tid  = threadIdx.x;
    const int warp = tid >> 5;
    const int lane = tid & 31;
    const int lg   = lane >> 2;
    const int lt   = lane & 3;
    const int wm   = warp >> 2;
    const int wn   = warp & 3;
    const int bm   = blockIdx.y * GBM;
    const int bn   = blockIdx.x * GBN;

    if (tid == 0) {
        MBAR_INIT(smb + SM_MB + 0,  1);
        MBAR_INIT(smb + SM_MB + 8,  1);
        MBAR_INIT(smb + SM_MB + 16, 1);
    }
    __syncthreads();

    auto issue = [&](int kc, int stg) {
        if (tid == 0)
            MBAR_EXPECT_TX(smb + SM_MB + stg * 8, (uint32_t)TILE_TX);
        if (lane == 0) {
            const uint32_t mb = smb + SM_MB + stg * 8;
            const __half* Ap = A + (size_t)bm * D + kc * GBK;
            uint32_t a_dst = smb + SM_A + stg * STAGE_B + (warp * 16) * (KS_H * 2);
#pragma unroll
            for (int r = 0; r < 16; r++)
                BULK_LD(a_dst + r * (KS_H * 2),
                        Ap + (size_t)(warp * 16 + r) * D, 128u, mb);
            const __half* Bp = B + (size_t)bn * D + kc * GBK;
            uint32_t b_dst = smb + SM_B + stg * STAGE_B + (warp * 16) * (KS_H * 2);
#pragma unroll
            for (int r = 0; r < 16; r++)
                BULK_LD(b_dst + r * (KS_H * 2),
                        Bp + (size_t)(warp * 16 + r) * D, 128u, mb);
        }
    };

    float c[4][4][4];
#pragma unroll
    for (int mi = 0; mi < 4; mi++)
#pragma unroll
        for (int ni = 0; ni < 4; ni++)
#pragma unroll
            for (int r = 0; r < 4; r++) c[mi][ni][r] = 0.0f;

    // ldmatrix per-thread address components (byte offsets within a stage)
    // A x4: row = wm*64 + mi*16 + (lane&15), khalf-base = (lane>>4)*8
    // B x4: row = wn*32 + nj*16 + (lane&7) + ((lane>>4)&1)*8,
    //       khalf-base = ((lane>>3)&1)*8
    const uint32_t a_row_off =
        (uint32_t)(wm * 64 + (lane & 15)) * (KS_H * 2) + ((lane >> 4) << 3) * 2;
    const uint32_t b_row_off =
        (uint32_t)(wn * 32 + (lane & 7) + (((lane >> 4) & 1) << 3)) * (KS_H * 2)
        + (((lane >> 3) & 1) << 3) * 2;

    const int nk = D / GBK;   // 64
    issue(0, 0);
    issue(1, 1);
    issue(2, 2);

    for (int kc = 0; kc < nk; kc++) {
        const int stg = kc % NSTAGE;
        mbar_wait(smb + SM_MB + stg * 8, (uint32_t)((kc / NSTAGE) & 1));

        const uint32_t aBase = smb + SM_A + stg * STAGE_B + a_row_off;
        const uint32_t bBase = smb + SM_B + stg * STAGE_B + b_row_off;
#pragma unroll
        for (int ks = 0; ks < GBK / 16; ks++) {      // 4 K=16 steps
            const uint32_t kb = ks * 32;             // 16 halves = 32 B
            uint32_t af[4][4];
#pragma unroll
            for (int mi = 0; mi < 4; mi++)
                LDSM_X4(af[mi][0], af[mi][1], af[mi][2], af[mi][3],
                        aBase + mi * 16 * (KS_H * 2) + kb);
            uint32_t bf[4][2];
#pragma unroll
            for (int nj = 0; nj < 2; nj++)
                LDSM_X4(bf[nj * 2][0], bf[nj * 2][1],
                        bf[nj * 2 + 1][0], bf[nj * 2 + 1][1],
                        bBase + nj * 16 * (KS_H * 2) + kb);
#pragma unroll
            for (int mi = 0; mi < 4; mi++)
#pragma unroll
                for (int ni = 0; ni < 4; ni++)
                    MMA_F16(c[mi][ni][0], c[mi][ni][1], c[mi][ni][2], c[mi][ni][3],
                            af[mi][0], af[mi][1], af[mi][2], af[mi][3],
                            bf[ni][0], bf[ni][1]);
        }
        __syncthreads();
        if (kc + NSTAGE < nk)
            issue(kc + NSTAGE, stg);
    }

#pragma unroll
    for (int mi = 0; mi < 4; mi++) {
        int r0 = bm + wm * 64 + mi * 16 + lg;
#pragma unroll
        for (int ni = 0; ni < 4; ni++) {
            int col = bn + wn * 32 + ni * 8 + lt * 2;
            *(float2*)(C + (size_t)r0 * D + col) =
                make_float2(c[mi][ni][0], c[mi][ni][1]);
            *(float2*)(C + (size_t)(r0 + 8) * D + col) =
                make_float2(c[mi][ni][2], c[mi][ni][3]);
        }
    }
}

// ---------------------------------------------------------------------------
// RoPE over full D: pair (i, i+2048) per thread, in-place (fp32 q/k).
// ---------------------------------------------------------------------------
__global__ __launch_bounds__(256) void rope_kernel(
    float* __restrict__ x, const float* __restrict__ cosp,
    const float* __restrict__ sinp)
{
    int idx = blockIdx.x * blockDim.x + threadIdx.x;
    int s = idx >> 11;
    int i = idx & 2047;
    size_t base = (size_t)s * D;
    float lo = x[base + i];
    float hi = x[base + i + 2048];
    float c1 = cosp[base + i];
    float s1 = sinp[base + i];
    float c2 = cosp[base + i + 2048];
    float s2 = sinp[base + i + 2048];
    x[base + i]        = lo * c1 - hi * s1;
    x[base + i + 2048] = hi * c2 + lo * s2;
}

// ---------------------------------------------------------------------------
// Flash attention with mma.sync tf32 (unchanged from R8 pass).
// Epilogue writes fp16 (feeds fp16 WO GEMM).
// ---------------------------------------------------------------------------
#define AQB 128
#define AKC 64
#define KVS 132
#define PS  68
#define ASM_K 0
#define ASM_V (AKC * KVS)
#define ASM_P (2 * AKC * KVS)
#define ATTN_SMEM ((2 * AKC * KVS + AQB * PS) * 4)   // 102400 B

__global__ __launch_bounds__(256, 1) void attn_kernel(
    const float* __restrict__ Q, const float* __restrict__ K,
    const float* __restrict__ V, const float* __restrict__ amask,
    __half* __restrict__ O)
{
    extern __shared__ float sm[];
    float* Ks = sm + ASM_K;
    float* Vs = sm + ASM_V;
    float* Pm = sm + ASM_P;
    const uint32_t* Ksb = (const uint32_t*)Ks;
    const uint32_t* Vsb = (const uint32_t*)Vs;
    const uint32_t* Pmb = (const uint32_t*)Pm;

    const int tid  = threadIdx.x;
    const int w    = tid >> 5;
    const int lane = tid & 31;
    const int lg   = lane >> 2;
    const int lt   = lane & 3;
    const int qb   = blockIdx.x * AQB;
    const int h0   = blockIdx.y * HD;
    const int rl0  = w * 16 + lg;
    const int r0   = qb + rl0;
    const int r1   = r0 + 8;

    uint32_t qf[16][4];
    {
        const float* Qp0 = Q + (size_t)r0 * D + h0;
        const float* Qp1 = Qp0 + 8 * (size_t)D;
#pragma unroll
        for (int ks = 0; ks < 16; ks++) {
            qf[ks][0] = cvt_tf32(Qp0[ks * 8 + lt]);
            qf[ks][1] = cvt_tf32(Qp1[ks * 8 + lt]);
            qf[ks][2] = cvt_tf32(Qp0[ks * 8 + lt + 4]);
            qf[ks][3] = cvt_tf32(Qp1[ks * 8 + lt + 4]);
        }
    }

    float o[16][4];
#pragma unroll
    for (int ni = 0; ni < 16; ni++)
#pragma unroll
        for (int r = 0; r < 4; r++) o[ni][r] = 0.0f;
    float m0 = -INFINITY, m1 = -INFINITY, l0 = 0.0f, l1 = 0.0f;

    const int kc0 = (qb == S - AQB) ? 0 : qb;

    for (int kc = kc0; kc < S; kc += AKC) {
        __syncthreads();
#pragma unroll
        for (int l = 0; l < 8; l++) {
            int id = tid + l * 256;
            int r  = id >> 5;
            int c4 = (id & 31) << 2;
            float4 kv = *(const float4*)(K + (size_t)(kc + r) * D + h0 + c4);
            float4 vv = *(const float4*)(V + (size_t)(kc + r) * D + h0 + c4);
            uint4 kr, vr;
            kr.x = cvt_tf32(kv.x); kr.y = cvt_tf32(kv.y);
            kr.z = cvt_tf32(kv.z); kr.w = cvt_tf32(kv.w);
            vr.x = cvt_tf32(vv.x); vr.y = cvt_tf32(vv.y);
            vr.z = cvt_tf32(vv.z); vr.w = cvt_tf32(vv.w);
            *(uint4*)(Ks + r * KVS + c4) = kr;
            *(uint4*)(Vs + r * KVS + c4) = vr;
        }
#pragma unroll
        for (int l = 0; l < 8; l++) {
            int id = tid + l * 256;
            int r  = id >> 4;
            int c4 = (id & 15) << 2;
            *(float4*)(Pm + r * PS + c4) =
                *(const float4*)(amask + (size_t)(qb + r) * S + kc + c4);
        }
        __syncthreads();

        float s[8][4];
#pragma unroll
        for (int ni = 0; ni < 8; ni++)
#pragma unroll
            for (int r = 0; r < 4; r++) s[ni][r] = 0.0f;
#pragma unroll
        for (int ks = 0; ks < 16; ks++) {
            const int kk = ks * 8;
#pragma unroll
            for (int ni = 0; ni < 8; ni++) {
                uint32_t b0 = Ksb[(ni * 8 + lg) * KVS + kk + lt];
                uint32_t b1 = Ksb[(ni * 8 + lg) * KVS + kk + lt + 4];
                MMA_TF32(s[ni][0], s[ni][1], s[ni][2], s[ni][3],
                         qf[ks][0], qf[ks][1], qf[ks][2], qf[ks][3], b0, b1);
            }
        }

        float mx0 = -INFINITY, mx1 = -INFINITY;
#pragma unroll
        for (int ni = 0; ni < 8; ni++) {
            int col = ni * 8 + lt * 2;
            int key = kc + col;
            float a00 = Pm[rl0 * PS + col], a01 = Pm[rl0 * PS + col + 1];
            float a10 = Pm[(rl0 + 8) * PS + col], a11 = Pm[(rl0 + 8) * PS + col + 1];
            float v0 = s[ni][0] * 0.015625f + a00;
            float v1 = s[ni][1] * 0.015625f + a01;
            float v2 = s[ni][2] * 0.015625f + a10;
            float v3 = s[ni][3] * 0.015625f + a11;
            if (key     <= r0) v0 += NEGV;
            if (key + 1 <= r0) v1 += NEGV;
            if (key     <= r1) v2 += NEGV;
            if (key + 1 <= r1) v3 += NEGV;
            s[ni][0] = v0; s[ni][1] = v1; s[ni][2] = v2; s[ni][3] = v3;
            mx0 = fmaxf(mx0, fmaxf(v0, v1));
            mx1 = fmaxf(mx1, fmaxf(v2, v3));
        }
        mx0 = fmaxf(mx0, __shfl_xor_sync(0xffffffffu, mx0, 1));
        mx0 = fmaxf(mx0, __shfl_xor_sync(0xffffffffu, mx0, 2));
        mx1 = fmaxf(mx1, __shfl_xor_sync(0xffffffffu, mx1, 1));
        mx1 = fmaxf(mx1, __shfl_xor_sync(0xffffffffu, mx1, 2));

        float nm0 = fmaxf(m0, mx0), nm1 = fmaxf(m1, mx1);
        float corr0 = __expf(m0 - nm0), corr1 = __expf(m1 - nm1);
        float ls0 = 0.0f, ls1 = 0.0f;
#pragma unroll
        for (int ni = 0; ni < 8; ni++) {
            int col = ni * 8 + lt * 2;
            float p0 = __expf(s[ni][0] - nm0);
            float p1 = __expf(s[ni][1] - nm0);
            float p2 = __expf(s[ni][2] - nm1);
            float p3 = __expf(s[ni][3] - nm1);
            ls0 += p0 + p1;
            ls1 += p2 + p3;
            Pm[rl0 * PS + col]           = __uint_as_float(cvt_tf32(p0));
            Pm[rl0 * PS + col + 1]       = __uint_as_float(cvt_tf32(p1));
            Pm[(rl0 + 8) * PS + col]     = __uint_as_float(cvt_tf32(p2));
            Pm[(rl0 + 8) * PS + col + 1] = __uint_as_float(cvt_tf32(p3));
        }
        ls0 += __shfl_xor_sync(0xffffffffu, ls0, 1);
        ls0 += __shfl_xor_sync(0xffffffffu, ls0, 2);
        ls1 += __shfl_xor_sync(0xffffffffu, ls1, 1);
        ls1 += __shfl_xor_sync(0xffffffffu, ls1, 2);
        l0 = l0 * corr0 + ls0;
        l1 = l1 * corr1 + ls1;
        m0 = nm0; m1 = nm1;
#pragma unroll
        for (int ni = 0; ni < 16; ni++) {
            o[ni][0] *= corr0; o[ni][1] *= corr0;
            o[ni][2] *= corr1; o[ni][3] *= corr1;
        }
        __syncwarp();

#pragma unroll
        for (int ks = 0; ks < 8; ks++) {
            const int kk = ks * 8;
            uint32_t a0 = Pmb[rl0 * PS + kk + lt];
            uint32_t a1 = Pmb[(rl0 + 8) * PS + kk + lt];
            uint32_t a2 = Pmb[rl0 * PS + kk + lt + 4];
            uint32_t a3 = Pmb[(rl0 + 8) * PS + kk + lt + 4];
#pragma unroll
            for (int ni = 0; ni < 16; ni++) {
                uint32_t b0 = Vsb[(kk + lt) * KVS + ni * 8 + lg];
                uint32_t b1 = Vsb[(kk + lt + 4) * KVS + ni * 8 + lg];
                MMA_TF32(o[ni][0], o[ni][1], o[ni][2], o[ni][3],
                         a0, a1, a2, a3, b0, b1);
            }
        }
    }

    float inv0 = 1.0f / l0, inv1 = 1.0f / l1;
#pragma unroll
    for (int ni = 0; ni < 16; ni++) {
        int col = ni * 8 + lt * 2;
        __half2 w0 = __floats2half2_rn(o[ni][0] * inv0, o[ni][1] * inv0);
        __half2 w1 = __floats2half2_rn(o[ni][2] * inv1, o[ni][3] * inv1);
        *(__half2*)(O + (size_t)r0 * D + h0 + col) = w0;
        *(__half2*)(O + (size_t)r1 * D + h0 + col) = w1;
    }
}

// ---------------------------------------------------------------------------
extern "C" void kernel_launch(void* const* d_in, const int* in_sizes, int n_in,
                              void* d_out, int out_size)
{
    const float* hidden = (const float*)d_in[0];
    const float* amask  = (const float*)d_in[1];
    const float* cosp   = (const float*)d_in[2];
    const float* sinp   = (const float*)d_in[3];
    const float* wq     = (const float*)d_in[4];
    const float* wk     = (const float*)d_in[5];
    const float* wv     = (const float*)d_in[6];
    const float* wo     = (const float*)d_in[7];
    float* out = (float*)d_out;

    float *q, *k, *v;
    __half *hh, *wth, *aoh;
    cudaGetSymbolAddress((void**)&q,   g_q);
    cudaGetSymbolAddress((void**)&k,   g_k);
    cudaGetSymbolAddress((void**)&v,   g_v);
    cudaGetSymbolAddress((void**)&hh,  g_hh);
    cudaGetSymbolAddress((void**)&wth, g_wth);
    cudaGetSymbolAddress((void**)&aoh, g_aoh);

    cudaFuncSetAttribute(attn_kernel,
                         cudaFuncAttributeMaxDynamicSharedMemorySize, ATTN_SMEM);
    cudaFuncSetAttribute(hgemm_kernel,
                         cudaFuncAttributeMaxDynamicSharedMemorySize, GEMM_SMEM);

    convert_h_kernel<<<(S * D) / (256 * 4), 256>>>(hidden, hh);
    transpose_w_kernel<<<dim3(D / 32, D / 32, 4), dim3(32, 8)>>>(
        wq, wk, wv, wo, wth);

    dim3 qkv_grid(D / GBN, S / GBM, 3);
    hgemm_kernel<<<qkv_grid, 256, GEMM_SMEM>>>(
        hh, wth, (size_t)D * D, q, k, v);

    int nrope = S * (D / 2);
    rope_kernel<<<nrope / 256, 256>>>(q, cosp, sinp);
    rope_kernel<<<nrope / 256, 256>>>(k, cosp, sinp);

    attn_kernel<<<dim3(S / AQB, H), 256, ATTN_SMEM>>>(q, k, v, amask, aoh);

    dim3 o_grid(D / GBN, S / GBM, 1);
    hgemm_kernel<<<o_grid, 256, GEMM_SMEM>>>(
        aoh, wth + 3 * (size_t)D * D, 0, out, out, out);
}